// round 1
// baseline (speedup 1.0000x reference)
#include <cuda_runtime.h>

#define D_MODEL 1024
#define NHEAD 16
#define HEAD_DIM 64
#define BATCH 2
#define SEQ 2048
#define MTOT (BATCH*SEQ)

// Scratch (no allocation allowed): Q/K/V in [B,H,N,Dh], attn out in [B,N,C]
__device__ float g_Q[BATCH*NHEAD*SEQ*HEAD_DIM];
__device__ float g_K[BATCH*NHEAD*SEQ*HEAD_DIM];
__device__ float g_V[BATCH*NHEAD*SEQ*HEAD_DIM];
__device__ float g_A[MTOT*D_MODEL];

// ---------------------------------------------------------------------------
// Core 128x128x1024 fp32 GEMM tile:  out[m,n] = sum_k A[m,k] * W[n,k]
// (both operands K-contiguous, "NT" layout). 256 threads, 8x8 per thread,
// microtile split 4+4 across each half of the 128 tile to reduce LDS conflicts.
// ---------------------------------------------------------------------------
__device__ __forceinline__ void sgemm_tile(const float* __restrict__ A,
                                           const float* __restrict__ W,
                                           int m0, int n0,
                                           float (&acc)[8][8],
                                           float* As, float* Bs)
{
    const int tid = threadIdx.x;
    const int lr  = tid >> 1;          // 0..127  row within tile
    const int lc  = (tid & 1) << 2;    // 0 or 4  k-offset
    const int ty  = tid >> 4;          // 0..15
    const int tx  = tid & 15;          // 0..15

    const float* aptr = A + (size_t)(m0 + lr) * D_MODEL + lc;
    const float* bptr = W + (size_t)(n0 + lr) * D_MODEL + lc;

    for (int kk = 0; kk < D_MODEL; kk += 8) {
        float4 av = *(const float4*)(aptr + kk);
        float4 bv = *(const float4*)(bptr + kk);
        __syncthreads();
        As[(lc+0)*128 + lr] = av.x;
        As[(lc+1)*128 + lr] = av.y;
        As[(lc+2)*128 + lr] = av.z;
        As[(lc+3)*128 + lr] = av.w;
        Bs[(lc+0)*128 + lr] = bv.x;
        Bs[(lc+1)*128 + lr] = bv.y;
        Bs[(lc+2)*128 + lr] = bv.z;
        Bs[(lc+3)*128 + lr] = bv.w;
        __syncthreads();
        #pragma unroll
        for (int k = 0; k < 8; k++) {
            float4 a0 = *(const float4*)(As + k*128 + ty*4);
            float4 a1 = *(const float4*)(As + k*128 + 64 + ty*4);
            float4 b0 = *(const float4*)(Bs + k*128 + tx*4);
            float4 b1 = *(const float4*)(Bs + k*128 + 64 + tx*4);
            float ar[8] = {a0.x,a0.y,a0.z,a0.w,a1.x,a1.y,a1.z,a1.w};
            float br[8] = {b0.x,b0.y,b0.z,b0.w,b1.x,b1.y,b1.z,b1.w};
            #pragma unroll
            for (int i = 0; i < 8; i++)
                #pragma unroll
                for (int j = 0; j < 8; j++)
                    acc[i][j] += ar[i] * br[j];
        }
    }
}

// ---------------------------------------------------------------------------
// Fused QKV projection. blockIdx.y in [0,24): 0-7 Q tiles, 8-15 K, 16-23 V.
// Epilogue applies bias + bipolar transform (scale 1/8 folded into Q) and
// scatters into [B,H,N,Dh] layout.
// ---------------------------------------------------------------------------
__global__ void __launch_bounds__(256) qkv_kernel(
    const float* __restrict__ X,
    const float* __restrict__ Wq, const float* __restrict__ bq,
    const float* __restrict__ Wk, const float* __restrict__ bk,
    const float* __restrict__ Wv, const float* __restrict__ bv)
{
    __shared__ float As[8*128];
    __shared__ float Bs[8*128];

    const int m0    = blockIdx.x * 128;
    const int tnn   = blockIdx.y;
    const int which = tnn >> 3;          // 0=Q 1=K 2=V
    const int n0    = (tnn & 7) * 128;

    const float* W    = (which == 0) ? Wq : ((which == 1) ? Wk : Wv);
    const float* bias = (which == 0) ? bq : ((which == 1) ? bk : bv);
    float*       dst  = (which == 0) ? g_Q : ((which == 1) ? g_K : g_V);

    float acc[8][8];
    #pragma unroll
    for (int i = 0; i < 8; i++)
        #pragma unroll
        for (int j = 0; j < 8; j++) acc[i][j] = 0.f;

    sgemm_tile(X, W, m0, n0, acc, As, Bs);

    const int ty = threadIdx.x >> 4;
    const int tx = threadIdx.x & 15;

    #pragma unroll
    for (int i = 0; i < 8; i++) {
        const int m   = m0 + ty*4 + ((i < 4) ? i : i + 60);
        const int b   = m >> 11;
        const int tok = m & 2047;
        #pragma unroll
        for (int j = 0; j < 8; j++) {
            const int gn = n0 + tx*4 + ((j < 4) ? j : j + 60);
            float v = acc[i][j] + bias[gn];
            if (which == 0)      v = (2.f*v - 1.f) * 0.125f;  // qb * 1/sqrt(Dh)
            else if (which == 1) v = 2.f*v - 1.f;             // kb
            const int h = gn >> 6, d = gn & 63;
            dst[(((size_t)(b*NHEAD + h))*SEQ + tok)*HEAD_DIM + d] = v;
        }
    }
}

// ---------------------------------------------------------------------------
// Flash attention, fp32. One block per (bh, 64-query tile). 256 threads as
// 16x16; each thread computes a 4x4 S tile and 4x4 O tile. Kt and Ps share one
// smem buffer (phases are disjoint). Online softmax state replicated across
// the 16 threads of each row group via shfl reductions.
// smem: Qt [64][64] (d-major) | KP [64][68] | Vs [64][64]  = 50176 B dynamic.
// ---------------------------------------------------------------------------
__global__ void __launch_bounds__(256) flash_kernel()
{
    extern __shared__ float sm[];
    float* Qt = sm;              // Qt[d*64 + r]
    float* KP = sm + 64*64;      // Kt[d*68 + k]  then  Ps[r*68 + k]
    float* Vs = KP + 64*68;      // Vs[k*64 + d]

    const int bh = blockIdx.y;
    const int q0 = blockIdx.x * 64;
    const float* Qp = g_Q + (size_t)bh * SEQ * HEAD_DIM;
    const float* Kp = g_K + (size_t)bh * SEQ * HEAD_DIM;
    const float* Vp = g_V + (size_t)bh * SEQ * HEAD_DIM;

    const int tid = threadIdx.x;
    const int ty = tid >> 4;
    const int tx = tid & 15;

    // Load Q tile transposed (d-major)
    for (int i = tid; i < 64*16; i += 256) {
        const int r = i >> 4;
        const int c = (i & 15) << 2;
        float4 qv = *(const float4*)(Qp + (size_t)(q0 + r)*HEAD_DIM + c);
        Qt[(c+0)*64 + r] = qv.x;
        Qt[(c+1)*64 + r] = qv.y;
        Qt[(c+2)*64 + r] = qv.z;
        Qt[(c+3)*64 + r] = qv.w;
    }

    float m_i[4], l_i[4], o[4][4];
    #pragma unroll
    for (int i = 0; i < 4; i++) {
        m_i[i] = -1e30f;
        l_i[i] = 0.f;
        #pragma unroll
        for (int j = 0; j < 4; j++) o[i][j] = 0.f;
    }

    for (int t = 0; t < SEQ/64; t++) {
        const int k0 = t * 64;
        __syncthreads();   // prior iteration done reading KP(Ps)/Vs
        for (int i = tid; i < 64*16; i += 256) {
            const int r = i >> 4;
            const int c = (i & 15) << 2;
            float4 kv = *(const float4*)(Kp + (size_t)(k0 + r)*HEAD_DIM + c);
            KP[(c+0)*68 + r] = kv.x;
            KP[(c+1)*68 + r] = kv.y;
            KP[(c+2)*68 + r] = kv.z;
            KP[(c+3)*68 + r] = kv.w;
            float4 vv = *(const float4*)(Vp + (size_t)(k0 + r)*HEAD_DIM + c);
            *(float4*)(Vs + r*64 + c) = vv;
        }
        __syncthreads();

        // S = Qb @ Kb^T  (scale prefolded into Q)
        float s[4][4];
        #pragma unroll
        for (int i = 0; i < 4; i++)
            #pragma unroll
            for (int j = 0; j < 4; j++) s[i][j] = 0.f;

        #pragma unroll 16
        for (int d = 0; d < 64; d++) {
            float4 a = *(const float4*)(Qt + d*64 + ty*4);
            float4 b = *(const float4*)(KP + d*68 + tx*4);
            float ar[4] = {a.x, a.y, a.z, a.w};
            float br[4] = {b.x, b.y, b.z, b.w};
            #pragma unroll
            for (int i = 0; i < 4; i++)
                #pragma unroll
                for (int j = 0; j < 4; j++)
                    s[i][j] += ar[i] * br[j];
        }

        // Online softmax. Row groups are 16 lanes (aligned within a warp half),
        // so xor-shuffles 1,2,4,8 reduce over the full row.
        #pragma unroll
        for (int i = 0; i < 4; i++) {
            float mx = fmaxf(fmaxf(s[i][0], s[i][1]), fmaxf(s[i][2], s[i][3]));
            #pragma unroll
            for (int off = 1; off < 16; off <<= 1)
                mx = fmaxf(mx, __shfl_xor_sync(0xffffffffu, mx, off));
            const float newm = fmaxf(m_i[i], mx);
            const float corr = __expf(m_i[i] - newm);
            m_i[i] = newm;
            float rs = 0.f;
            #pragma unroll
            for (int j = 0; j < 4; j++) {
                s[i][j] = __expf(s[i][j] - newm);
                rs += s[i][j];
            }
            #pragma unroll
            for (int off = 1; off < 16; off <<= 1)
                rs += __shfl_xor_sync(0xffffffffu, rs, off);
            l_i[i] = l_i[i] * corr + rs;
            #pragma unroll
            for (int j = 0; j < 4; j++) o[i][j] *= corr;
        }

        __syncthreads();   // everyone done reading KP as Kt
        #pragma unroll
        for (int i = 0; i < 4; i++)
            *(float4*)(KP + (ty*4 + i)*68 + tx*4) =
                make_float4(s[i][0], s[i][1], s[i][2], s[i][3]);
        __syncthreads();   // Ps visible

        // O += P @ V
        #pragma unroll 16
        for (int k = 0; k < 64; k++) {
            float4 b = *(const float4*)(Vs + k*64 + tx*4);
            #pragma unroll
            for (int i = 0; i < 4; i++) {
                const float a = KP[(ty*4 + i)*68 + k];
                o[i][0] += a * b.x;
                o[i][1] += a * b.y;
                o[i][2] += a * b.z;
                o[i][3] += a * b.w;
            }
        }
    }

    // Normalize and write in [B, N, C] layout
    const int b = bh >> 4;
    const int h = bh & 15;
    #pragma unroll
    for (int i = 0; i < 4; i++) {
        const float inv = 1.f / l_i[i];
        const int row = q0 + ty*4 + i;
        *(float4*)(g_A + ((size_t)(b*SEQ) + row)*D_MODEL + h*HEAD_DIM + tx*4) =
            make_float4(o[i][0]*inv, o[i][1]*inv, o[i][2]*inv, o[i][3]*inv);
    }
}

// ---------------------------------------------------------------------------
// Output projection: d_out = g_A @ Wo^T + bo
// ---------------------------------------------------------------------------
__global__ void __launch_bounds__(256) proj_kernel(
    const float* __restrict__ Wo, const float* __restrict__ bo,
    float* __restrict__ out)
{
    __shared__ float As[8*128];
    __shared__ float Bs[8*128];

    const int m0 = blockIdx.x * 128;
    const int n0 = blockIdx.y * 128;

    float acc[8][8];
    #pragma unroll
    for (int i = 0; i < 8; i++)
        #pragma unroll
        for (int j = 0; j < 8; j++) acc[i][j] = 0.f;

    sgemm_tile(g_A, Wo, m0, n0, acc, As, Bs);

    const int ty = threadIdx.x >> 4;
    const int tx = threadIdx.x & 15;
    #pragma unroll
    for (int i = 0; i < 8; i++) {
        const int m = m0 + ty*4 + ((i < 4) ? i : i + 60);
        #pragma unroll
        for (int j = 0; j < 8; j++) {
            const int gn = n0 + tx*4 + ((j < 4) ? j : j + 60);
            out[(size_t)m * D_MODEL + gn] = acc[i][j] + bo[gn];
        }
    }
}

extern "C" void kernel_launch(void* const* d_in, const int* in_sizes, int n_in,
                              void* d_out, int out_size)
{
    const float* x  = (const float*)d_in[0];
    const float* Wq = (const float*)d_in[1];
    const float* bq = (const float*)d_in[2];
    const float* Wk = (const float*)d_in[3];
    const float* bk = (const float*)d_in[4];
    const float* Wv = (const float*)d_in[5];
    const float* bv = (const float*)d_in[6];
    const float* Wo = (const float*)d_in[7];
    const float* bo = (const float*)d_in[8];
    float* out = (float*)d_out;

    qkv_kernel<<<dim3(32, 24), 256>>>(x, Wq, bq, Wk, bk, Wv, bv);

    const int smem = (64*64 + 64*68 + 64*64) * (int)sizeof(float); // 50176 B
    cudaFuncSetAttribute(flash_kernel,
                         cudaFuncAttributeMaxDynamicSharedMemorySize, smem);
    flash_kernel<<<dim3(SEQ/64, BATCH*NHEAD), 256, smem>>>();

    proj_kernel<<<dim3(32, 8), 256>>>(Wo, bo, out);
}

// round 3
// speedup vs baseline: 1.2492x; 1.2492x over previous
#include <cuda_runtime.h>
#include <cstdint>

#define D_MODEL 1024
#define NHEAD 16
#define HEAD_DIM 64
#define BATCH 2
#define SEQ 2048
#define MTOT (BATCH*SEQ)

// Scratch (no allocation allowed)
__device__ float g_Q[BATCH*NHEAD*SEQ*HEAD_DIM];
__device__ float g_K[BATCH*NHEAD*SEQ*HEAD_DIM];
__device__ float g_V[BATCH*NHEAD*SEQ*HEAD_DIM];
__device__ float g_A[MTOT*D_MODEL];

__device__ __forceinline__ uint32_t f2tf(float f) {
    uint32_t u;
    asm("cvt.rna.tf32.f32 %0, %1;" : "=r"(u) : "f"(f));
    return u;
}

// hi/lo split: together ~21 mantissa bits of x
__device__ __forceinline__ void split_store(uint32_t* H, uint32_t* L,
                                            int idx, float x) {
    uint32_t h = f2tf(x);
    H[idx] = h;
    L[idx] = f2tf(x - __uint_as_float(h));
}

__device__ __forceinline__ void mma8(float (&d)[4], const uint32_t (&a)[4],
                                     const uint32_t (&b)[2]) {
    asm volatile(
        "mma.sync.aligned.m16n8k8.row.col.f32.tf32.tf32.f32 "
        "{%0,%1,%2,%3}, {%4,%5,%6,%7}, {%8,%9}, {%0,%1,%2,%3};"
        : "+f"(d[0]), "+f"(d[1]), "+f"(d[2]), "+f"(d[3])
        : "r"(a[0]), "r"(a[1]), "r"(a[2]), "r"(a[3]),
          "r"(b[0]), "r"(b[1]));
}

// ---------------------------------------------------------------------------
// 3xTF32 GEMM tile 128x128, K=1024. out[m,n] = sum_k A[m,k]*W[n,k].
// 256 threads = 8 warps (2x4), each warp 64x32 via m16n8k8.
// Smem [k][m] stride 132, hi+lo planes, double buffered (KSTG=8).
// ---------------------------------------------------------------------------
#define KSTG 8
#define SSTR 132
#define SBUF (KSTG*SSTR)

__device__ __forceinline__ void mma_gemm(const float* __restrict__ A,
                                         const float* __restrict__ W,
                                         int m0, int n0,
                                         float (&acc)[4][4][4],
                                         uint32_t* Ah, uint32_t* Al,
                                         uint32_t* Bh, uint32_t* Bl)
{
    const int tid  = threadIdx.x;
    const int lane = tid & 31;
    const int warp = tid >> 5;
    const int wm   = (warp >> 2) * 64;
    const int wn   = (warp & 3) * 32;
    const int lr   = tid >> 1;          // 0..127 row
    const int kc   = (tid & 1) * 4;     // 0 or 4 k-offset

    const float* ap = A + (size_t)(m0 + lr) * D_MODEL + kc;
    const float* bp = W + (size_t)(n0 + lr) * D_MODEL + kc;

    float4 av = *(const float4*)ap;
    float4 bv = *(const float4*)bp;

    // stage 0 store
    split_store(Ah, Al, (kc+0)*SSTR+lr, av.x);
    split_store(Ah, Al, (kc+1)*SSTR+lr, av.y);
    split_store(Ah, Al, (kc+2)*SSTR+lr, av.z);
    split_store(Ah, Al, (kc+3)*SSTR+lr, av.w);
    split_store(Bh, Bl, (kc+0)*SSTR+lr, bv.x);
    split_store(Bh, Bl, (kc+1)*SSTR+lr, bv.y);
    split_store(Bh, Bl, (kc+2)*SSTR+lr, bv.z);
    split_store(Bh, Bl, (kc+3)*SSTR+lr, bv.w);
    __syncthreads();

    const int k = lane & 3;
    int buf = 0;
    #pragma unroll 1
    for (int s = 0; s < D_MODEL / KSTG; s++) {
        if (s < D_MODEL/KSTG - 1) {
            av = *(const float4*)(ap + (s + 1) * KSTG);
            bv = *(const float4*)(bp + (s + 1) * KSTG);
        }
        const uint32_t* AH = Ah + buf * SBUF;
        const uint32_t* AL = Al + buf * SBUF;
        const uint32_t* BH = Bh + buf * SBUF;
        const uint32_t* BL = Bl + buf * SBUF;

        uint32_t ah[4][4], al[4][4];
        #pragma unroll
        for (int mt = 0; mt < 4; mt++) {
            const int m = wm + mt*16 + (lane >> 2);
            ah[mt][0] = AH[k*SSTR + m];      ah[mt][1] = AH[k*SSTR + m + 8];
            ah[mt][2] = AH[(k+4)*SSTR + m];  ah[mt][3] = AH[(k+4)*SSTR + m + 8];
            al[mt][0] = AL[k*SSTR + m];      al[mt][1] = AL[k*SSTR + m + 8];
            al[mt][2] = AL[(k+4)*SSTR + m];  al[mt][3] = AL[(k+4)*SSTR + m + 8];
        }
        #pragma unroll
        for (int nt = 0; nt < 4; nt++) {
            const int n = wn + nt*8 + (lane >> 2);
            uint32_t bh2[2] = { BH[k*SSTR + n], BH[(k+4)*SSTR + n] };
            uint32_t bl2[2] = { BL[k*SSTR + n], BL[(k+4)*SSTR + n] };
            #pragma unroll
            for (int mt = 0; mt < 4; mt++) {
                mma8(acc[mt][nt], ah[mt], bh2);   // hi*hi
                mma8(acc[mt][nt], al[mt], bh2);   // lo*hi
                mma8(acc[mt][nt], ah[mt], bl2);   // hi*lo
            }
        }

        if (s < D_MODEL/KSTG - 1) {
            uint32_t* AH2 = Ah + (buf^1) * SBUF;
            uint32_t* AL2 = Al + (buf^1) * SBUF;
            uint32_t* BH2 = Bh + (buf^1) * SBUF;
            uint32_t* BL2 = Bl + (buf^1) * SBUF;
            split_store(AH2, AL2, (kc+0)*SSTR+lr, av.x);
            split_store(AH2, AL2, (kc+1)*SSTR+lr, av.y);
            split_store(AH2, AL2, (kc+2)*SSTR+lr, av.z);
            split_store(AH2, AL2, (kc+3)*SSTR+lr, av.w);
            split_store(BH2, BL2, (kc+0)*SSTR+lr, bv.x);
            split_store(BH2, BL2, (kc+1)*SSTR+lr, bv.y);
            split_store(BH2, BL2, (kc+2)*SSTR+lr, bv.z);
            split_store(BH2, BL2, (kc+3)*SSTR+lr, bv.w);
        }
        __syncthreads();
        buf ^= 1;
    }
}

// ---------------------------------------------------------------------------
// Fused QKV projection. blockIdx.y: 0-7 Q, 8-15 K, 16-23 V.
// ---------------------------------------------------------------------------
__global__ void __launch_bounds__(256, 2) qkv_kernel(
    const float* __restrict__ X,
    const float* __restrict__ Wq, const float* __restrict__ bq,
    const float* __restrict__ Wk, const float* __restrict__ bk,
    const float* __restrict__ Wv, const float* __restrict__ bv)
{
    __shared__ uint32_t Ah[2*SBUF], Al[2*SBUF];
    __shared__ uint32_t Bh[2*SBUF], Bl[2*SBUF];

    const int m0    = blockIdx.x * 128;
    const int tnn   = blockIdx.y;
    const int which = tnn >> 3;
    const int n0    = (tnn & 7) * 128;

    const float* W    = (which == 0) ? Wq : ((which == 1) ? Wk : Wv);
    const float* bias = (which == 0) ? bq : ((which == 1) ? bk : bv);
    float*       dst  = (which == 0) ? g_Q : ((which == 1) ? g_K : g_V);

    float acc[4][4][4];
    #pragma unroll
    for (int i = 0; i < 4; i++)
        #pragma unroll
        for (int j = 0; j < 4; j++)
            #pragma unroll
            for (int c = 0; c < 4; c++) acc[i][j][c] = 0.f;

    mma_gemm(X, W, m0, n0, acc, Ah, Al, Bh, Bl);

    const int lane = threadIdx.x & 31;
    const int warp = threadIdx.x >> 5;
    const int wm = (warp >> 2) * 64;
    const int wn = (warp & 3) * 32;

    #pragma unroll
    for (int mt = 0; mt < 4; mt++) {
        #pragma unroll
        for (int half = 0; half < 2; half++) {
            const int row = m0 + wm + mt*16 + (lane >> 2) + half*8;
            const int b   = row >> 11;
            const int tok = row & 2047;
            #pragma unroll
            for (int nt = 0; nt < 4; nt++) {
                const int col = n0 + wn + nt*8 + 2*(lane & 3);
                float v0 = acc[mt][nt][half*2+0] + bias[col];
                float v1 = acc[mt][nt][half*2+1] + bias[col+1];
                if (which == 0) { v0 = (2.f*v0 - 1.f)*0.125f; v1 = (2.f*v1 - 1.f)*0.125f; }
                else if (which == 1) { v0 = 2.f*v0 - 1.f; v1 = 2.f*v1 - 1.f; }
                const int h = col >> 6, d = col & 63;
                *(float2*)(dst + (((size_t)(b*NHEAD + h))*SEQ + tok)*HEAD_DIM + d)
                    = make_float2(v0, v1);
            }
        }
    }
}

// ---------------------------------------------------------------------------
// Flash attention. Br=128, Bc=64. Scores use 3xTF32 (Q hi/lo in registers,
// K hi/lo in smem). PV stays single tf32 (P in [0,1], well-conditioned).
// smem: Qs/Ps 128x68 | Ks_hi 64x68 | Ks_lo 64x68 | Vs 64x72 = 88064 B.
// ---------------------------------------------------------------------------
#define QSTR 68
#define KSTR 68
#define VSTR 72

__global__ void __launch_bounds__(256, 1) flash_kernel()
{
    extern __shared__ float sm[];
    float*    Qs  = sm;                          // later reused as Ps
    uint32_t* Ps  = (uint32_t*)sm;
    uint32_t* Ksh = (uint32_t*)(sm + 128*QSTR);
    uint32_t* Ksl = Ksh + 64*KSTR;
    uint32_t* Vs  = Ksl + 64*KSTR;

    const int bh = blockIdx.y;
    const int q0 = blockIdx.x * 128;
    const float* Qp = g_Q + (size_t)bh * SEQ * HEAD_DIM;
    const float* Kp = g_K + (size_t)bh * SEQ * HEAD_DIM;
    const float* Vp = g_V + (size_t)bh * SEQ * HEAD_DIM;

    const int tid  = threadIdx.x;
    const int lane = tid & 31;
    const int warp = tid >> 5;
    const int r0   = warp*16 + (lane >> 2);

    // Stage Q tile, extract persistent hi/lo A-fragments
    for (int i = tid; i < 128*16; i += 256) {
        const int r = i >> 4, c = (i & 15) << 2;
        *(float4*)(Qs + r*QSTR + c) =
            *(const float4*)(Qp + (size_t)(q0 + r)*HEAD_DIM + c);
    }
    __syncthreads();

    uint32_t qh[8][4], ql[8][4];
    #pragma unroll
    for (int kg = 0; kg < 8; kg++) {
        const int k = kg*8 + (lane & 3);
        float q0v = Qs[r0*QSTR + k];
        float q1v = Qs[(r0+8)*QSTR + k];
        float q2v = Qs[r0*QSTR + k + 4];
        float q3v = Qs[(r0+8)*QSTR + k + 4];
        qh[kg][0] = f2tf(q0v); ql[kg][0] = f2tf(q0v - __uint_as_float(qh[kg][0]));
        qh[kg][1] = f2tf(q1v); ql[kg][1] = f2tf(q1v - __uint_as_float(qh[kg][1]));
        qh[kg][2] = f2tf(q2v); ql[kg][2] = f2tf(q2v - __uint_as_float(qh[kg][2]));
        qh[kg][3] = f2tf(q3v); ql[kg][3] = f2tf(q3v - __uint_as_float(qh[kg][3]));
    }

    float m_i[2] = {-1e30f, -1e30f};
    float l_i[2] = {0.f, 0.f};
    float o[8][4];
    #pragma unroll
    for (int nt = 0; nt < 8; nt++)
        #pragma unroll
        for (int c = 0; c < 4; c++) o[nt][c] = 0.f;

    for (int t = 0; t < SEQ/64; t++) {
        const int k0 = t * 64;
        __syncthreads();
        for (int i = tid; i < 64*16; i += 256) {
            const int r = i >> 4, c = (i & 15) << 2;
            float4 kv = *(const float4*)(Kp + (size_t)(k0 + r)*HEAD_DIM + c);
            split_store(Ksh, Ksl, r*KSTR + c + 0, kv.x);
            split_store(Ksh, Ksl, r*KSTR + c + 1, kv.y);
            split_store(Ksh, Ksl, r*KSTR + c + 2, kv.z);
            split_store(Ksh, Ksl, r*KSTR + c + 3, kv.w);
            float4 vv = *(const float4*)(Vp + (size_t)(k0 + r)*HEAD_DIM + c);
            Vs[r*VSTR + c + 0] = f2tf(vv.x);
            Vs[r*VSTR + c + 1] = f2tf(vv.y);
            Vs[r*VSTR + c + 2] = f2tf(vv.z);
            Vs[r*VSTR + c + 3] = f2tf(vv.w);
        }
        __syncthreads();

        // S = Qb @ Kb^T, 3xTF32
        float s[8][4];
        #pragma unroll
        for (int nt = 0; nt < 8; nt++)
            #pragma unroll
            for (int c = 0; c < 4; c++) s[nt][c] = 0.f;

        #pragma unroll
        for (int kg = 0; kg < 8; kg++) {
            const int k = kg*8 + (lane & 3);
            #pragma unroll
            for (int nt = 0; nt < 8; nt++) {
                const int n = nt*8 + (lane >> 2);
                uint32_t bh2[2] = { Ksh[n*KSTR + k], Ksh[n*KSTR + k + 4] };
                uint32_t bl2[2] = { Ksl[n*KSTR + k], Ksl[n*KSTR + k + 4] };
                mma8(s[nt], qh[kg], bh2);
                mma8(s[nt], ql[kg], bh2);
                mma8(s[nt], qh[kg], bl2);
            }
        }

        // Online softmax (row split across 4 lanes)
        float mx0 = -1e30f, mx1 = -1e30f;
        #pragma unroll
        for (int nt = 0; nt < 8; nt++) {
            mx0 = fmaxf(mx0, fmaxf(s[nt][0], s[nt][1]));
            mx1 = fmaxf(mx1, fmaxf(s[nt][2], s[nt][3]));
        }
        mx0 = fmaxf(mx0, __shfl_xor_sync(0xffffffffu, mx0, 1));
        mx0 = fmaxf(mx0, __shfl_xor_sync(0xffffffffu, mx0, 2));
        mx1 = fmaxf(mx1, __shfl_xor_sync(0xffffffffu, mx1, 1));
        mx1 = fmaxf(mx1, __shfl_xor_sync(0xffffffffu, mx1, 2));

        const float nm0 = fmaxf(m_i[0], mx0);
        const float nm1 = fmaxf(m_i[1], mx1);
        const float cr0 = __expf(m_i[0] - nm0);
        const float cr1 = __expf(m_i[1] - nm1);
        m_i[0] = nm0; m_i[1] = nm1;

        float rs0 = 0.f, rs1 = 0.f;
        #pragma unroll
        for (int nt = 0; nt < 8; nt++) {
            s[nt][0] = __expf(s[nt][0] - nm0);
            s[nt][1] = __expf(s[nt][1] - nm0);
            s[nt][2] = __expf(s[nt][2] - nm1);
            s[nt][3] = __expf(s[nt][3] - nm1);
            rs0 += s[nt][0] + s[nt][1];
            rs1 += s[nt][2] + s[nt][3];
        }
        rs0 += __shfl_xor_sync(0xffffffffu, rs0, 1);
        rs0 += __shfl_xor_sync(0xffffffffu, rs0, 2);
        rs1 += __shfl_xor_sync(0xffffffffu, rs1, 1);
        rs1 += __shfl_xor_sync(0xffffffffu, rs1, 2);
        l_i[0] = l_i[0]*cr0 + rs0;
        l_i[1] = l_i[1]*cr1 + rs1;

        #pragma unroll
        for (int nt = 0; nt < 8; nt++) {
            o[nt][0] *= cr0; o[nt][1] *= cr0;
            o[nt][2] *= cr1; o[nt][3] *= cr1;
        }

        // Store P (tf32, single) to this warp's rows of Ps
        #pragma unroll
        for (int nt = 0; nt < 8; nt++) {
            const int col = nt*8 + 2*(lane & 3);
            Ps[r0*QSTR + col]         = f2tf(s[nt][0]);
            Ps[r0*QSTR + col + 1]     = f2tf(s[nt][1]);
            Ps[(r0+8)*QSTR + col]     = f2tf(s[nt][2]);
            Ps[(r0+8)*QSTR + col + 1] = f2tf(s[nt][3]);
        }
        __syncwarp();

        // O += P @ V (single tf32)
        #pragma unroll
        for (int kg = 0; kg < 8; kg++) {
            const int k = kg*8 + (lane & 3);
            uint32_t pa[4] = { Ps[r0*QSTR + k],     Ps[(r0+8)*QSTR + k],
                               Ps[r0*QSTR + k + 4], Ps[(r0+8)*QSTR + k + 4] };
            #pragma unroll
            for (int nt = 0; nt < 8; nt++) {
                const int n = nt*8 + (lane >> 2);
                uint32_t bf[2] = { Vs[k*VSTR + n], Vs[(k+4)*VSTR + n] };
                mma8(o[nt], pa, bf);
            }
        }
        __syncwarp();
    }

    // Normalize + write [B, N, C]
    const int b = bh >> 4;
    const int h = bh & 15;
    const float inv0 = 1.f / l_i[0];
    const float inv1 = 1.f / l_i[1];
    #pragma unroll
    for (int nt = 0; nt < 8; nt++) {
        const int d = h*64 + nt*8 + 2*(lane & 3);
        *(float2*)(g_A + ((size_t)(b*SEQ) + q0 + r0)*D_MODEL + d)
            = make_float2(o[nt][0]*inv0, o[nt][1]*inv0);
        *(float2*)(g_A + ((size_t)(b*SEQ) + q0 + r0 + 8)*D_MODEL + d)
            = make_float2(o[nt][2]*inv1, o[nt][3]*inv1);
    }
}

// ---------------------------------------------------------------------------
// Output projection: d_out = g_A @ Wo^T + bo
// ---------------------------------------------------------------------------
__global__ void __launch_bounds__(256, 2) proj_kernel(
    const float* __restrict__ Wo, const float* __restrict__ bo,
    float* __restrict__ out)
{
    __shared__ uint32_t Ah[2*SBUF], Al[2*SBUF];
    __shared__ uint32_t Bh[2*SBUF], Bl[2*SBUF];

    const int m0 = blockIdx.x * 128;
    const int n0 = blockIdx.y * 128;

    float acc[4][4][4];
    #pragma unroll
    for (int i = 0; i < 4; i++)
        #pragma unroll
        for (int j = 0; j < 4; j++)
            #pragma unroll
            for (int c = 0; c < 4; c++) acc[i][j][c] = 0.f;

    mma_gemm(g_A, Wo, m0, n0, acc, Ah, Al, Bh, Bl);

    const int lane = threadIdx.x & 31;
    const int warp = threadIdx.x >> 5;
    const int wm = (warp >> 2) * 64;
    const int wn = (warp & 3) * 32;

    #pragma unroll
    for (int mt = 0; mt < 4; mt++) {
        #pragma unroll
        for (int half = 0; half < 2; half++) {
            const int row = m0 + wm + mt*16 + (lane >> 2) + half*8;
            #pragma unroll
            for (int nt = 0; nt < 4; nt++) {
                const int col = n0 + wn + nt*8 + 2*(lane & 3);
                float v0 = acc[mt][nt][half*2+0] + bo[col];
                float v1 = acc[mt][nt][half*2+1] + bo[col+1];
                *(float2*)(out + (size_t)row * D_MODEL + col) = make_float2(v0, v1);
            }
        }
    }
}

extern "C" void kernel_launch(void* const* d_in, const int* in_sizes, int n_in,
                              void* d_out, int out_size)
{
    const float* x  = (const float*)d_in[0];
    const float* Wq = (const float*)d_in[1];
    const float* bq = (const float*)d_in[2];
    const float* Wk = (const float*)d_in[3];
    const float* bk = (const float*)d_in[4];
    const float* Wv = (const float*)d_in[5];
    const float* bv = (const float*)d_in[6];
    const float* Wo = (const float*)d_in[7];
    const float* bo = (const float*)d_in[8];
    float* out = (float*)d_out;

    qkv_kernel<<<dim3(32, 24), 256>>>(x, Wq, bq, Wk, bk, Wv, bv);

    const int smem = (128*QSTR + 2*64*KSTR + 64*VSTR) * (int)sizeof(float); // 88064
    cudaFuncSetAttribute(flash_kernel,
                         cudaFuncAttributeMaxDynamicSharedMemorySize, smem);
    flash_kernel<<<dim3(SEQ/128, BATCH*NHEAD), 256, smem>>>();

    proj_kernel<<<dim3(32, 8), 256>>>(Wo, bo, out);
}

// round 4
// speedup vs baseline: 2.0380x; 1.6315x over previous
#include <cuda_runtime.h>
#include <cuda_bf16.h>
#include <cstdint>

#define D_MODEL 1024
#define NHEAD 16
#define HEAD_DIM 64
#define BATCH 2
#define SEQ 2048
#define MTOT (BATCH*SEQ)

// Scratch (no allocation allowed)
__device__ float g_Q[BATCH*NHEAD*SEQ*HEAD_DIM];
__device__ float g_K[BATCH*NHEAD*SEQ*HEAD_DIM];
__device__ float g_V[BATCH*NHEAD*SEQ*HEAD_DIM];
__device__ float g_A[MTOT*D_MODEL];

// round-to-nearest-even truncation to bf16, returned as float
__device__ __forceinline__ float bf_hi(float x) {
    uint32_t u = __float_as_uint(x);
    uint32_t hb = (u + 0x7fffu + ((u >> 16) & 1u)) & 0xffff0000u;
    return __uint_as_float(hb);
}

// pack two floats as bf16x2: e0 -> low half (even k), e1 -> high half
__device__ __forceinline__ uint32_t pack_bf2(float e0, float e1) {
    uint32_t r;
    asm("cvt.rn.bf16x2.f32 %0, %1, %2;" : "=r"(r) : "f"(e1), "f"(e0));
    return r;
}

__device__ __forceinline__ void mma16(float (&d)[4], const uint32_t (&a)[4],
                                      const uint32_t (&b)[2]) {
    asm volatile(
        "mma.sync.aligned.m16n8k16.row.col.f32.bf16.bf16.f32 "
        "{%0,%1,%2,%3}, {%4,%5,%6,%7}, {%8,%9}, {%0,%1,%2,%3};"
        : "+f"(d[0]), "+f"(d[1]), "+f"(d[2]), "+f"(d[3])
        : "r"(a[0]), "r"(a[1]), "r"(a[2]), "r"(a[3]),
          "r"(b[0]), "r"(b[1]));
}

// ---------------------------------------------------------------------------
// bf16 2-split GEMM tile 128x128, K=1024. out[m,n] = sum_k A[m,k]*W[n,k].
// 8 warps (2x4), warp tile 64x32 via m16n8k16. Stage = k16 (8 packed words).
// Smem planes [word 0..7][row], stride 136 words, XOR-16 row swizzle for
// words 4..7 -> conflict-free stores AND fragment loads (verified).
// ---------------------------------------------------------------------------
#define SSTR 136
#define SBUF (8*SSTR)

__device__ __forceinline__ int sphys(int w, int r) {
    return w * SSTR + (r ^ ((w & 4) << 2));   // xor 16 when w in [4,8)
}

__device__ __forceinline__ void stage_store(uint32_t* H, uint32_t* L,
                                            int wb, int lr,
                                            float4 v0, float4 v1) {
    float e[8] = {v0.x, v0.y, v0.z, v0.w, v1.x, v1.y, v1.z, v1.w};
    #pragma unroll
    for (int j = 0; j < 4; j++) {
        float h0 = bf_hi(e[2*j]), h1 = bf_hi(e[2*j+1]);
        const int a = sphys(wb + j, lr);
        H[a] = pack_bf2(h0, h1);
        L[a] = pack_bf2(e[2*j] - h0, e[2*j+1] - h1);
    }
}

__device__ __forceinline__ void mma_gemm(const float* __restrict__ A,
                                         const float* __restrict__ W,
                                         int m0, int n0,
                                         float (&acc)[4][4][4],
                                         uint32_t* Ah, uint32_t* Al,
                                         uint32_t* Bh, uint32_t* Bl)
{
    const int tid  = threadIdx.x;
    const int lane = tid & 31;
    const int warp = tid >> 5;
    const int wm   = (warp >> 2) * 64;
    const int wn   = (warp & 3) * 32;
    const int lr   = tid >> 1;           // 0..127 row
    const int wb   = (tid & 1) * 4;      // word group 0..3 / 4..7
    const int kw   = lane & 3;
    const int l4   = lane >> 2;

    const float* ap = A + (size_t)(m0 + lr) * D_MODEL + wb * 2;
    const float* bp = W + (size_t)(n0 + lr) * D_MODEL + wb * 2;

    float4 av0 = *(const float4*)ap;
    float4 av1 = *(const float4*)(ap + 4);
    float4 bv0 = *(const float4*)bp;
    float4 bv1 = *(const float4*)(bp + 4);

    stage_store(Ah, Al, wb, lr, av0, av1);
    stage_store(Bh, Bl, wb, lr, bv0, bv1);
    __syncthreads();

    int buf = 0;
    #pragma unroll 1
    for (int s = 0; s < D_MODEL / 16; s++) {
        if (s < D_MODEL/16 - 1) {
            const float* ap2 = ap + (s + 1) * 16;
            const float* bp2 = bp + (s + 1) * 16;
            av0 = *(const float4*)ap2;   av1 = *(const float4*)(ap2 + 4);
            bv0 = *(const float4*)bp2;   bv1 = *(const float4*)(bp2 + 4);
        }
        const uint32_t* AH = Ah + buf * SBUF;
        const uint32_t* AL = Al + buf * SBUF;
        const uint32_t* BH = Bh + buf * SBUF;
        const uint32_t* BL = Bl + buf * SBUF;

        uint32_t ah[4][4], al[4][4];
        #pragma unroll
        for (int mt = 0; mt < 4; mt++) {
            const int m = wm + mt*16 + l4;
            ah[mt][0] = AH[sphys(kw,   m)];   ah[mt][1] = AH[sphys(kw,   m+8)];
            ah[mt][2] = AH[sphys(kw+4, m)];   ah[mt][3] = AH[sphys(kw+4, m+8)];
            al[mt][0] = AL[sphys(kw,   m)];   al[mt][1] = AL[sphys(kw,   m+8)];
            al[mt][2] = AL[sphys(kw+4, m)];   al[mt][3] = AL[sphys(kw+4, m+8)];
        }
        #pragma unroll
        for (int nt = 0; nt < 4; nt++) {
            const int n = wn + nt*8 + l4;
            uint32_t bh2[2] = { BH[sphys(kw, n)], BH[sphys(kw+4, n)] };
            uint32_t bl2[2] = { BL[sphys(kw, n)], BL[sphys(kw+4, n)] };
            #pragma unroll
            for (int mt = 0; mt < 4; mt++) {
                mma16(acc[mt][nt], ah[mt], bh2);   // hi*hi
                mma16(acc[mt][nt], al[mt], bh2);   // lo*hi
                mma16(acc[mt][nt], ah[mt], bl2);   // hi*lo
            }
        }

        if (s < D_MODEL/16 - 1) {
            stage_store(Ah + (buf^1)*SBUF, Al + (buf^1)*SBUF, wb, lr, av0, av1);
            stage_store(Bh + (buf^1)*SBUF, Bl + (buf^1)*SBUF, wb, lr, bv0, bv1);
        }
        __syncthreads();
        buf ^= 1;
    }
}

// ---------------------------------------------------------------------------
// Fused QKV projection. blockIdx.y: 0-7 Q, 8-15 K, 16-23 V.
// ---------------------------------------------------------------------------
__global__ void __launch_bounds__(256, 2) qkv_kernel(
    const float* __restrict__ X,
    const float* __restrict__ Wq, const float* __restrict__ bq,
    const float* __restrict__ Wk, const float* __restrict__ bk,
    const float* __restrict__ Wv, const float* __restrict__ bv)
{
    __shared__ uint32_t Ah[2*SBUF], Al[2*SBUF];
    __shared__ uint32_t Bh[2*SBUF], Bl[2*SBUF];

    const int m0    = blockIdx.x * 128;
    const int tnn   = blockIdx.y;
    const int which = tnn >> 3;
    const int n0    = (tnn & 7) * 128;

    const float* W    = (which == 0) ? Wq : ((which == 1) ? Wk : Wv);
    const float* bias = (which == 0) ? bq : ((which == 1) ? bk : bv);
    float*       dst  = (which == 0) ? g_Q : ((which == 1) ? g_K : g_V);

    float acc[4][4][4];
    #pragma unroll
    for (int i = 0; i < 4; i++)
        #pragma unroll
        for (int j = 0; j < 4; j++)
            #pragma unroll
            for (int c = 0; c < 4; c++) acc[i][j][c] = 0.f;

    mma_gemm(X, W, m0, n0, acc, Ah, Al, Bh, Bl);

    const int lane = threadIdx.x & 31;
    const int warp = threadIdx.x >> 5;
    const int wm = (warp >> 2) * 64;
    const int wn = (warp & 3) * 32;

    #pragma unroll
    for (int mt = 0; mt < 4; mt++) {
        #pragma unroll
        for (int half = 0; half < 2; half++) {
            const int row = m0 + wm + mt*16 + (lane >> 2) + half*8;
            const int b   = row >> 11;
            const int tok = row & 2047;
            #pragma unroll
            for (int nt = 0; nt < 4; nt++) {
                const int col = n0 + wn + nt*8 + 2*(lane & 3);
                float v0 = acc[mt][nt][half*2+0] + bias[col];
                float v1 = acc[mt][nt][half*2+1] + bias[col+1];
                if (which == 0) { v0 = (2.f*v0 - 1.f)*0.125f; v1 = (2.f*v1 - 1.f)*0.125f; }
                else if (which == 1) { v0 = 2.f*v0 - 1.f; v1 = 2.f*v1 - 1.f; }
                const int h = col >> 6, d = col & 63;
                *(float2*)(dst + (((size_t)(b*NHEAD + h))*SEQ + tok)*HEAD_DIM + d)
                    = make_float2(v0, v1);
            }
        }
    }
}

// ---------------------------------------------------------------------------
// Flash attention, bf16 2-split, m16n8k16. Br=128 (16 q-rows/warp), Bc=64.
// Q fragments from gmem into registers; K/V staged hi/lo packed in smem.
// S C-fragments double directly as PV A-fragments -> P never hits smem.
// smem: Kh,Kl [64][36w] + Vh,Vl [32 keywords][72w] = 36864 B.
// ---------------------------------------------------------------------------
__global__ void __launch_bounds__(256, 2) flash_kernel()
{
    __shared__ uint32_t Kh[64*36], Kl[64*36];
    __shared__ uint32_t Vh[32*72], Vl[32*72];

    const int bh = blockIdx.y;
    const int q0 = blockIdx.x * 128;
    const float* Qp = g_Q + (size_t)bh * SEQ * HEAD_DIM;
    const float* Kp = g_K + (size_t)bh * SEQ * HEAD_DIM;
    const float* Vp = g_V + (size_t)bh * SEQ * HEAD_DIM;

    const int tid  = threadIdx.x;
    const int lane = tid & 31;
    const int warp = tid >> 5;
    const int l4   = lane >> 2;
    const int lk   = lane & 3;
    const int r0   = warp*16 + l4;

    // Q fragments (hi/lo) straight from gmem
    uint32_t qh[4][4], ql[4][4];
    #pragma unroll
    for (int kg = 0; kg < 4; kg++) {
        const int c0 = kg*16 + lk*2;
        const float* qr0 = Qp + (size_t)(q0 + r0) * HEAD_DIM;
        const float* qr1 = qr0 + 8 * HEAD_DIM;
        float2 x00 = *(const float2*)(qr0 + c0);
        float2 x10 = *(const float2*)(qr1 + c0);
        float2 x01 = *(const float2*)(qr0 + c0 + 8);
        float2 x11 = *(const float2*)(qr1 + c0 + 8);
        float h0, h1;
        h0 = bf_hi(x00.x); h1 = bf_hi(x00.y);
        qh[kg][0] = pack_bf2(h0, h1); ql[kg][0] = pack_bf2(x00.x-h0, x00.y-h1);
        h0 = bf_hi(x10.x); h1 = bf_hi(x10.y);
        qh[kg][1] = pack_bf2(h0, h1); ql[kg][1] = pack_bf2(x10.x-h0, x10.y-h1);
        h0 = bf_hi(x01.x); h1 = bf_hi(x01.y);
        qh[kg][2] = pack_bf2(h0, h1); ql[kg][2] = pack_bf2(x01.x-h0, x01.y-h1);
        h0 = bf_hi(x11.x); h1 = bf_hi(x11.y);
        qh[kg][3] = pack_bf2(h0, h1); ql[kg][3] = pack_bf2(x11.x-h0, x11.y-h1);
    }

    float m_i[2] = {-1e30f, -1e30f};
    float l_i[2] = {0.f, 0.f};
    float o[8][4];
    #pragma unroll
    for (int nt = 0; nt < 8; nt++)
        #pragma unroll
        for (int c = 0; c < 4; c++) o[nt][c] = 0.f;

    const int kkey = lane & 7, kwrd = lane >> 3;   // K staging map
    const int va   = lane >> 3, vd   = lane & 7;   // V staging map

    for (int t = 0; t < SEQ/64; t++) {
        const int k0 = t * 64;
        __syncthreads();   // previous iteration done reading tiles

        // K: [key][dim-word] packed pairs along head dim; stride 36 words
        #pragma unroll
        for (int it = 0; it < 8; it++) {
            const int wi  = warp*8 + it;
            const int key = (wi >> 3)*8 + kkey;
            const int w   = (wi & 7)*4 + kwrd;
            float2 kv = *(const float2*)(Kp + (size_t)(k0 + key)*HEAD_DIM + w*2);
            float h0 = bf_hi(kv.x), h1 = bf_hi(kv.y);
            Kh[key*36 + w] = pack_bf2(h0, h1);
            Kl[key*36 + w] = pack_bf2(kv.x - h0, kv.y - h1);
        }
        // V transposed: [key-word][dim], packed pairs along key; stride 72
        #pragma unroll
        for (int it = 0; it < 8; it++) {
            const int wi = warp*8 + it;
            const int a  = (wi >> 3)*4 + va;
            const int d  = (wi & 7)*8 + vd;
            float v0 = Vp[(size_t)(k0 + 2*a    )*HEAD_DIM + d];
            float v1 = Vp[(size_t)(k0 + 2*a + 1)*HEAD_DIM + d];
            float h0 = bf_hi(v0), h1 = bf_hi(v1);
            Vh[a*72 + d] = pack_bf2(h0, h1);
            Vl[a*72 + d] = pack_bf2(v0 - h0, v1 - h1);
        }
        __syncthreads();

        // S = Qb @ Kb^T (3-term)
        float s[8][4];
        #pragma unroll
        for (int nt = 0; nt < 8; nt++)
            #pragma unroll
            for (int c = 0; c < 4; c++) s[nt][c] = 0.f;

        #pragma unroll
        for (int kg = 0; kg < 4; kg++) {
            const int kw = kg*8 + lk;
            #pragma unroll
            for (int nt = 0; nt < 8; nt++) {
                const int n = nt*8 + l4;
                uint32_t bh2[2] = { Kh[n*36 + kw], Kh[n*36 + kw + 4] };
                uint32_t bl2[2] = { Kl[n*36 + kw], Kl[n*36 + kw + 4] };
                mma16(s[nt], qh[kg], bh2);
                mma16(s[nt], ql[kg], bh2);
                mma16(s[nt], qh[kg], bl2);
            }
        }

        // Online softmax (rows split across 4 lanes)
        float mx0 = -1e30f, mx1 = -1e30f;
        #pragma unroll
        for (int nt = 0; nt < 8; nt++) {
            mx0 = fmaxf(mx0, fmaxf(s[nt][0], s[nt][1]));
            mx1 = fmaxf(mx1, fmaxf(s[nt][2], s[nt][3]));
        }
        mx0 = fmaxf(mx0, __shfl_xor_sync(0xffffffffu, mx0, 1));
        mx0 = fmaxf(mx0, __shfl_xor_sync(0xffffffffu, mx0, 2));
        mx1 = fmaxf(mx1, __shfl_xor_sync(0xffffffffu, mx1, 1));
        mx1 = fmaxf(mx1, __shfl_xor_sync(0xffffffffu, mx1, 2));

        const float nm0 = fmaxf(m_i[0], mx0);
        const float nm1 = fmaxf(m_i[1], mx1);
        const float cr0 = __expf(m_i[0] - nm0);
        const float cr1 = __expf(m_i[1] - nm1);
        m_i[0] = nm0; m_i[1] = nm1;

        float rs0 = 0.f, rs1 = 0.f;
        #pragma unroll
        for (int nt = 0; nt < 8; nt++) {
            s[nt][0] = __expf(s[nt][0] - nm0);
            s[nt][1] = __expf(s[nt][1] - nm0);
            s[nt][2] = __expf(s[nt][2] - nm1);
            s[nt][3] = __expf(s[nt][3] - nm1);
            rs0 += s[nt][0] + s[nt][1];
            rs1 += s[nt][2] + s[nt][3];
        }
        rs0 += __shfl_xor_sync(0xffffffffu, rs0, 1);
        rs0 += __shfl_xor_sync(0xffffffffu, rs0, 2);
        rs1 += __shfl_xor_sync(0xffffffffu, rs1, 1);
        rs1 += __shfl_xor_sync(0xffffffffu, rs1, 2);
        l_i[0] = l_i[0]*cr0 + rs0;
        l_i[1] = l_i[1]*cr1 + rs1;

        #pragma unroll
        for (int nt = 0; nt < 8; nt++) {
            o[nt][0] *= cr0; o[nt][1] *= cr0;
            o[nt][2] *= cr1; o[nt][3] *= cr1;
        }

        // O += P @ V : S C-frag IS the PV A-frag (keys are adjacent pairs)
        #pragma unroll
        for (int kg = 0; kg < 4; kg++) {
            float h00 = bf_hi(s[2*kg][0]),   h01 = bf_hi(s[2*kg][1]);
            float h02 = bf_hi(s[2*kg][2]),   h03 = bf_hi(s[2*kg][3]);
            float h10 = bf_hi(s[2*kg+1][0]), h11 = bf_hi(s[2*kg+1][1]);
            float h12 = bf_hi(s[2*kg+1][2]), h13 = bf_hi(s[2*kg+1][3]);
            uint32_t pah[4] = {
                pack_bf2(h00, h01), pack_bf2(h02, h03),
                pack_bf2(h10, h11), pack_bf2(h12, h13) };
            uint32_t pal[4] = {
                pack_bf2(s[2*kg][0]-h00,   s[2*kg][1]-h01),
                pack_bf2(s[2*kg][2]-h02,   s[2*kg][3]-h03),
                pack_bf2(s[2*kg+1][0]-h10, s[2*kg+1][1]-h11),
                pack_bf2(s[2*kg+1][2]-h12, s[2*kg+1][3]-h13) };
            const int kw = kg*8 + lk;
            #pragma unroll
            for (int nt = 0; nt < 8; nt++) {
                const int n = nt*8 + l4;
                uint32_t bh2[2] = { Vh[kw*72 + n], Vh[(kw+4)*72 + n] };
                uint32_t bl2[2] = { Vl[kw*72 + n], Vl[(kw+4)*72 + n] };
                mma16(o[nt], pah, bh2);
                mma16(o[nt], pal, bh2);
                mma16(o[nt], pah, bl2);
            }
        }
    }

    // Normalize + write [B, N, C]
    const int b = bh >> 4;
    const int h = bh & 15;
    const float inv0 = 1.f / l_i[0];
    const float inv1 = 1.f / l_i[1];
    #pragma unroll
    for (int nt = 0; nt < 8; nt++) {
        const int d = h*64 + nt*8 + 2*lk;
        *(float2*)(g_A + ((size_t)(b*SEQ) + q0 + r0)*D_MODEL + d)
            = make_float2(o[nt][0]*inv0, o[nt][1]*inv0);
        *(float2*)(g_A + ((size_t)(b*SEQ) + q0 + r0 + 8)*D_MODEL + d)
            = make_float2(o[nt][2]*inv1, o[nt][3]*inv1);
    }
}

// ---------------------------------------------------------------------------
// Output projection: d_out = g_A @ Wo^T + bo
// ---------------------------------------------------------------------------
__global__ void __launch_bounds__(256, 2) proj_kernel(
    const float* __restrict__ Wo, const float* __restrict__ bo,
    float* __restrict__ out)
{
    __shared__ uint32_t Ah[2*SBUF], Al[2*SBUF];
    __shared__ uint32_t Bh[2*SBUF], Bl[2*SBUF];

    const int m0 = blockIdx.x * 128;
    const int n0 = blockIdx.y * 128;

    float acc[4][4][4];
    #pragma unroll
    for (int i = 0; i < 4; i++)
        #pragma unroll
        for (int j = 0; j < 4; j++)
            #pragma unroll
            for (int c = 0; c < 4; c++) acc[i][j][c] = 0.f;

    mma_gemm(g_A, Wo, m0, n0, acc, Ah, Al, Bh, Bl);

    const int lane = threadIdx.x & 31;
    const int warp = threadIdx.x >> 5;
    const int wm = (warp >> 2) * 64;
    const int wn = (warp & 3) * 32;

    #pragma unroll
    for (int mt = 0; mt < 4; mt++) {
        #pragma unroll
        for (int half = 0; half < 2; half++) {
            const int row = m0 + wm + mt*16 + (lane >> 2) + half*8;
            #pragma unroll
            for (int nt = 0; nt < 4; nt++) {
                const int col = n0 + wn + nt*8 + 2*(lane & 3);
                float v0 = acc[mt][nt][half*2+0] + bo[col];
                float v1 = acc[mt][nt][half*2+1] + bo[col+1];
                *(float2*)(out + (size_t)row * D_MODEL + col) = make_float2(v0, v1);
            }
        }
    }
}

extern "C" void kernel_launch(void* const* d_in, const int* in_sizes, int n_in,
                              void* d_out, int out_size)
{
    const float* x  = (const float*)d_in[0];
    const float* Wq = (const float*)d_in[1];
    const float* bq = (const float*)d_in[2];
    const float* Wk = (const float*)d_in[3];
    const float* bk = (const float*)d_in[4];
    const float* Wv = (const float*)d_in[5];
    const float* bv = (const float*)d_in[6];
    const float* Wo = (const float*)d_in[7];
    const float* bo = (const float*)d_in[8];
    float* out = (float*)d_out;

    qkv_kernel<<<dim3(32, 24), 256>>>(x, Wq, bq, Wk, bk, Wv, bv);
    flash_kernel<<<dim3(SEQ/128, BATCH*NHEAD), 256>>>();
    proj_kernel<<<dim3(32, 8), 256>>>(Wo, bo, out);
}

// round 5
// speedup vs baseline: 2.1240x; 1.0422x over previous
#include <cuda_runtime.h>
#include <cuda_bf16.h>
#include <cstdint>

#define D_MODEL 1024
#define NHEAD 16
#define HEAD_DIM 64
#define BATCH 2
#define SEQ 2048
#define MTOT (BATCH*SEQ)
#define LDP 512              // plane row stride in words (D_MODEL/2)

// ---------------- scratch (no allocation allowed) -------------------------
__device__ uint32_t g_xh[MTOT*LDP], g_xl[MTOT*LDP];          // x planes
__device__ uint32_t g_Wh[4][D_MODEL*LDP], g_Wl[4][D_MODEL*LDP]; // Wq,Wk,Wv,Wo
__device__ uint32_t g_Qh[32*SEQ*32], g_Ql[32*SEQ*32];        // [bh][tok][32w]
__device__ uint32_t g_Kh[32*SEQ*32], g_Kl[32*SEQ*32];
__device__ float    g_V [32*SEQ*HEAD_DIM];
__device__ uint32_t g_Ah[MTOT*LDP], g_Al[MTOT*LDP];          // attn out planes

// ---------------- helpers -------------------------------------------------
__device__ __forceinline__ float bf_hi(float x) {
    uint32_t u = __float_as_uint(x);
    uint32_t hb = (u + 0x7fffu + ((u >> 16) & 1u)) & 0xffff0000u;
    return __uint_as_float(hb);
}
__device__ __forceinline__ uint32_t pack_bf2(float e0, float e1) {
    uint32_t r;
    asm("cvt.rn.bf16x2.f32 %0, %1, %2;" : "=r"(r) : "f"(e1), "f"(e0));
    return r;
}
__device__ __forceinline__ void mma16(float (&d)[4], const uint32_t (&a)[4],
                                      const uint32_t (&b)[2]) {
    asm volatile(
        "mma.sync.aligned.m16n8k16.row.col.f32.bf16.bf16.f32 "
        "{%0,%1,%2,%3}, {%4,%5,%6,%7}, {%8,%9}, {%0,%1,%2,%3};"
        : "+f"(d[0]), "+f"(d[1]), "+f"(d[2]), "+f"(d[3])
        : "r"(a[0]), "r"(a[1]), "r"(a[2]), "r"(a[3]),
          "r"(b[0]), "r"(b[1]));
}
__device__ __forceinline__ void ldsm4(uint32_t (&r)[4], uint32_t saddr) {
    asm volatile("ldmatrix.sync.aligned.m8n8.x4.shared.b16 {%0,%1,%2,%3}, [%4];"
                 : "=r"(r[0]), "=r"(r[1]), "=r"(r[2]), "=r"(r[3]) : "r"(saddr));
}

// ---------------------------------------------------------------------------
// Pre-conversion: fp32 -> packed bf16x2 hi/lo planes.
// blockIdx.y: 0..3 = quarters of x, 4..7 = Wq,Wk,Wv,Wo.
// ---------------------------------------------------------------------------
__global__ void __launch_bounds__(256) convert_kernel(
    const float* __restrict__ x,
    const float* __restrict__ Wq, const float* __restrict__ Wk,
    const float* __restrict__ Wv, const float* __restrict__ Wo)
{
    const int y = blockIdx.y;
    const float* src;
    uint32_t *dh, *dl;
    if (y < 4) { src = x + (size_t)y * 1048576; dh = g_xh + (size_t)y*524288; dl = g_xl + (size_t)y*524288; }
    else {
        src = (y == 4) ? Wq : (y == 5) ? Wk : (y == 6) ? Wv : Wo;
        dh = g_Wh[y-4]; dl = g_Wl[y-4];
    }
    const int idx = blockIdx.x * 256 + threadIdx.x;      // 1024 blocks
    float4 v = ((const float4*)src)[idx];
    float h0 = bf_hi(v.x), h1 = bf_hi(v.y), h2 = bf_hi(v.z), h3 = bf_hi(v.w);
    ((uint2*)dh)[idx] = make_uint2(pack_bf2(h0, h1), pack_bf2(h2, h3));
    ((uint2*)dl)[idx] = make_uint2(pack_bf2(v.x-h0, v.y-h1), pack_bf2(v.z-h2, v.w-h3));
}

// ---------------------------------------------------------------------------
// bf16 2-split GEMM core on packed planes. Tile 128x128, K=1024, KSTG=32.
// cp.async double-buffered; fragments via ldmatrix.x4; chunk swizzle
// phys = chunk ^ ((row>>1)&3) -> conflict-free loads & stores (verified).
// Smem: [2 buf][4 arrays (Ah,Al,Bh,Bl)][128 rows * 16 words] = 64 KB dynamic.
// ---------------------------------------------------------------------------
#define NS (D_MODEL/32)

__device__ __forceinline__ void mma_gemm_pl(
    const uint32_t* __restrict__ Aph, const uint32_t* __restrict__ Apl,
    const uint32_t* __restrict__ Bph, const uint32_t* __restrict__ Bpl,
    int m0, int n0, float (&acc)[4][4][4], uint32_t* sm)
{
    const int tid  = threadIdx.x;
    const int lane = tid & 31;
    const int warp = tid >> 5;
    const int wm   = (warp >> 2) * 64;
    const int wn   = (warp & 3) * 32;

    uint32_t sbase = (uint32_t)__cvta_generic_to_shared(sm);

    // copy assignment: 64 threads per array, 8 chunks (16B) each per stage
    const int arr = tid >> 6, u = tid & 63;
    const uint32_t* gp = (arr == 0) ? Aph : (arr == 1) ? Apl
                        : (arr == 2) ? Bph : Bpl;
    const int rbase = (arr < 2) ? m0 : n0;
    const int uph   = (u >> 1) & 3;

    #define ISSUE(S, BUF) do {                                               \
        _Pragma("unroll")                                                    \
        for (int c = 0; c < 8; c++) {                                        \
            const int row   = u + 64*(c>>2);                                 \
            const int chunk = c & 3;                                         \
            const int phys  = chunk ^ uph;                                   \
            uint32_t daddr = sbase + (((BUF)*8192 + arr*2048 + row*16 + phys*4) << 2); \
            const uint32_t* sp = gp + (size_t)(rbase + row)*LDP + (S)*16 + chunk*4; \
            asm volatile("cp.async.cg.shared.global [%0], [%1], 16;"         \
                         :: "r"(daddr), "l"(sp));                            \
        }                                                                    \
        asm volatile("cp.async.commit_group;");                              \
    } while (0)

    ISSUE(0, 0);

    int buf = 0;
    #pragma unroll 1
    for (int s = 0; s < NS; s++) {
        if (s + 1 < NS) {
            ISSUE(s + 1, buf ^ 1);
            asm volatile("cp.async.wait_group 1;");
        } else {
            asm volatile("cp.async.wait_group 0;");
        }
        __syncthreads();

        const uint32_t bb = sbase + ((buf*8192) << 2);
        #pragma unroll
        for (int kb = 0; kb < 2; kb++) {
            uint32_t ah[4][4], al[4][4];
            #pragma unroll
            for (int mt = 0; mt < 4; mt++) {
                const int row   = wm + mt*16 + (lane & 15);
                const int chunk = kb*2 + (lane >> 4);
                const int phys  = chunk ^ ((row >> 1) & 3);
                const uint32_t ad = bb + ((row*16 + phys*4) << 2);
                ldsm4(ah[mt], ad);
                ldsm4(al[mt], ad + (2048u << 2));
            }
            #pragma unroll
            for (int np = 0; np < 2; np++) {
                const int row   = wn + np*16 + (lane & 7) + ((lane & 16) ? 8 : 0);
                const int chunk = kb*2 + ((lane >> 3) & 1);
                const int phys  = chunk ^ ((row >> 1) & 3);
                const uint32_t bd = bb + ((2*2048 + row*16 + phys*4) << 2);
                uint32_t bh4[4], bl4[4];
                ldsm4(bh4, bd);
                ldsm4(bl4, bd + (2048u << 2));
                uint32_t b0h[2] = {bh4[0], bh4[1]}, b1h[2] = {bh4[2], bh4[3]};
                uint32_t b0l[2] = {bl4[0], bl4[1]}, b1l[2] = {bl4[2], bl4[3]};
                #pragma unroll
                for (int mt = 0; mt < 4; mt++) {
                    mma16(acc[mt][2*np],   ah[mt], b0h);
                    mma16(acc[mt][2*np],   al[mt], b0h);
                    mma16(acc[mt][2*np],   ah[mt], b0l);
                    mma16(acc[mt][2*np+1], ah[mt], b1h);
                    mma16(acc[mt][2*np+1], al[mt], b1h);
                    mma16(acc[mt][2*np+1], ah[mt], b1l);
                }
            }
        }
        __syncthreads();
        buf ^= 1;
    }
    #undef ISSUE
}

// ---------------------------------------------------------------------------
// Fused QKV projection. blockIdx.y: 0-7 Q, 8-15 K, 16-23 V.
// Q/K epilogue writes split-packed planes; V written fp32.
// ---------------------------------------------------------------------------
__global__ void __launch_bounds__(256, 2) qkv_kernel(
    const float* __restrict__ bq, const float* __restrict__ bk,
    const float* __restrict__ bv)
{
    extern __shared__ uint32_t sm[];

    const int m0    = blockIdx.x * 128;
    const int tnn   = blockIdx.y;
    const int which = tnn >> 3;
    const int n0    = (tnn & 7) * 128;
    const float* bias = (which == 0) ? bq : ((which == 1) ? bk : bv);

    float acc[4][4][4];
    #pragma unroll
    for (int i = 0; i < 4; i++)
        #pragma unroll
        for (int j = 0; j < 4; j++)
            #pragma unroll
            for (int c = 0; c < 4; c++) acc[i][j][c] = 0.f;

    mma_gemm_pl(g_xh, g_xl, g_Wh[which], g_Wl[which], m0, n0, acc, sm);

    const int lane = threadIdx.x & 31;
    const int warp = threadIdx.x >> 5;
    const int wm = (warp >> 2) * 64;
    const int wn = (warp & 3) * 32;

    #pragma unroll
    for (int mt = 0; mt < 4; mt++) {
        #pragma unroll
        for (int half = 0; half < 2; half++) {
            const int row = m0 + wm + mt*16 + (lane >> 2) + half*8;
            const int b   = row >> 11;
            const int tok = row & 2047;
            #pragma unroll
            for (int nt = 0; nt < 4; nt++) {
                const int col = n0 + wn + nt*8 + 2*(lane & 3);
                float v0 = acc[mt][nt][half*2+0] + bias[col];
                float v1 = acc[mt][nt][half*2+1] + bias[col+1];
                const int h = col >> 6, d = col & 63;
                const size_t bhrow = ((size_t)(b*NHEAD + h))*SEQ + tok;
                if (which == 2) {
                    *(float2*)(g_V + bhrow*HEAD_DIM + d) = make_float2(v0, v1);
                } else {
                    if (which == 0) { v0 = (2.f*v0 - 1.f)*0.125f; v1 = (2.f*v1 - 1.f)*0.125f; }
                    else            { v0 = 2.f*v0 - 1.f;          v1 = 2.f*v1 - 1.f; }
                    float h0 = bf_hi(v0), h1 = bf_hi(v1);
                    const size_t w = bhrow*32 + (d >> 1);
                    if (which == 0) {
                        g_Qh[w] = pack_bf2(h0, h1);
                        g_Ql[w] = pack_bf2(v0 - h0, v1 - h1);
                    } else {
                        g_Kh[w] = pack_bf2(h0, h1);
                        g_Kl[w] = pack_bf2(v0 - h0, v1 - h1);
                    }
                }
            }
        }
    }
}

// ---------------------------------------------------------------------------
// Flash attention, bf16 2-split. Br=128, Bc=64. Q frags direct from packed
// planes; K staging = pure packed copy; V transposed+split at stage time.
// Epilogue writes attention output as split-packed planes for proj.
// ---------------------------------------------------------------------------
__global__ void __launch_bounds__(256, 2) flash_kernel()
{
    __shared__ uint32_t Ksh[64*36], Ksl[64*36];
    __shared__ uint32_t Vh[32*72], Vl[32*72];

    const int bh = blockIdx.y;
    const int q0 = blockIdx.x * 128;
    const uint32_t* Qhp = g_Qh + (size_t)bh * SEQ * 32;
    const uint32_t* Qlp = g_Ql + (size_t)bh * SEQ * 32;
    const uint32_t* Khp = g_Kh + (size_t)bh * SEQ * 32;
    const uint32_t* Klp = g_Kl + (size_t)bh * SEQ * 32;
    const float*    Vp  = g_V  + (size_t)bh * SEQ * HEAD_DIM;

    const int tid  = threadIdx.x;
    const int lane = tid & 31;
    const int warp = tid >> 5;
    const int l4   = lane >> 2;
    const int lk   = lane & 3;
    const int r0   = warp*16 + l4;

    // Q fragments directly from packed planes
    uint32_t qh[4][4], ql[4][4];
    {
        const size_t r0w = (size_t)(q0 + r0) * 32;
        const size_t r1w = r0w + 8*32;
        #pragma unroll
        for (int kg = 0; kg < 4; kg++) {
            const int w = kg*8 + lk;
            qh[kg][0] = Qhp[r0w + w];     qh[kg][1] = Qhp[r1w + w];
            qh[kg][2] = Qhp[r0w + w + 4]; qh[kg][3] = Qhp[r1w + w + 4];
            ql[kg][0] = Qlp[r0w + w];     ql[kg][1] = Qlp[r1w + w];
            ql[kg][2] = Qlp[r0w + w + 4]; ql[kg][3] = Qlp[r1w + w + 4];
        }
    }

    float m_i[2] = {-1e30f, -1e30f};
    float l_i[2] = {0.f, 0.f};
    float o[8][4];
    #pragma unroll
    for (int nt = 0; nt < 8; nt++)
        #pragma unroll
        for (int c = 0; c < 4; c++) o[nt][c] = 0.f;

    const int va = lane >> 3, vd = lane & 7;    // V staging map

    for (int t = 0; t < SEQ/64; t++) {
        const int k0 = t * 64;
        __syncthreads();

        // K: straight packed copy, stride 36 words (conflict-free frag reads)
        #pragma unroll
        for (int it = 0; it < 8; it++) {
            const int i = it*256 + tid;
            const int key = i >> 5, w = i & 31;
            const size_t g = (size_t)(k0 + key)*32 + w;
            Ksh[key*36 + w] = Khp[g];
            Ksl[key*36 + w] = Klp[g];
        }
        // V transposed split: [key-word][dim], pairs along key; stride 72
        #pragma unroll
        for (int it = 0; it < 8; it++) {
            const int wi = warp*8 + it;
            const int a  = (wi >> 3)*4 + va;
            const int d  = (wi & 7)*8 + vd;
            float v0 = Vp[(size_t)(k0 + 2*a    )*HEAD_DIM + d];
            float v1 = Vp[(size_t)(k0 + 2*a + 1)*HEAD_DIM + d];
            float h0 = bf_hi(v0), h1 = bf_hi(v1);
            Vh[a*72 + d] = pack_bf2(h0, h1);
            Vl[a*72 + d] = pack_bf2(v0 - h0, v1 - h1);
        }
        __syncthreads();

        // S = Qb @ Kb^T (3-term)
        float s[8][4];
        #pragma unroll
        for (int nt = 0; nt < 8; nt++)
            #pragma unroll
            for (int c = 0; c < 4; c++) s[nt][c] = 0.f;

        #pragma unroll
        for (int kg = 0; kg < 4; kg++) {
            const int kw = kg*8 + lk;
            #pragma unroll
            for (int nt = 0; nt < 8; nt++) {
                const int n = nt*8 + l4;
                uint32_t bh2[2] = { Ksh[n*36 + kw], Ksh[n*36 + kw + 4] };
                uint32_t bl2[2] = { Ksl[n*36 + kw], Ksl[n*36 + kw + 4] };
                mma16(s[nt], qh[kg], bh2);
                mma16(s[nt], ql[kg], bh2);
                mma16(s[nt], qh[kg], bl2);
            }
        }

        // Online softmax
        float mx0 = -1e30f, mx1 = -1e30f;
        #pragma unroll
        for (int nt = 0; nt < 8; nt++) {
            mx0 = fmaxf(mx0, fmaxf(s[nt][0], s[nt][1]));
            mx1 = fmaxf(mx1, fmaxf(s[nt][2], s[nt][3]));
        }
        mx0 = fmaxf(mx0, __shfl_xor_sync(0xffffffffu, mx0, 1));
        mx0 = fmaxf(mx0, __shfl_xor_sync(0xffffffffu, mx0, 2));
        mx1 = fmaxf(mx1, __shfl_xor_sync(0xffffffffu, mx1, 1));
        mx1 = fmaxf(mx1, __shfl_xor_sync(0xffffffffu, mx1, 2));

        const float nm0 = fmaxf(m_i[0], mx0);
        const float nm1 = fmaxf(m_i[1], mx1);
        const float cr0 = __expf(m_i[0] - nm0);
        const float cr1 = __expf(m_i[1] - nm1);
        m_i[0] = nm0; m_i[1] = nm1;

        float rs0 = 0.f, rs1 = 0.f;
        #pragma unroll
        for (int nt = 0; nt < 8; nt++) {
            s[nt][0] = __expf(s[nt][0] - nm0);
            s[nt][1] = __expf(s[nt][1] - nm0);
            s[nt][2] = __expf(s[nt][2] - nm1);
            s[nt][3] = __expf(s[nt][3] - nm1);
            rs0 += s[nt][0] + s[nt][1];
            rs1 += s[nt][2] + s[nt][3];
        }
        rs0 += __shfl_xor_sync(0xffffffffu, rs0, 1);
        rs0 += __shfl_xor_sync(0xffffffffu, rs0, 2);
        rs1 += __shfl_xor_sync(0xffffffffu, rs1, 1);
        rs1 += __shfl_xor_sync(0xffffffffu, rs1, 2);
        l_i[0] = l_i[0]*cr0 + rs0;
        l_i[1] = l_i[1]*cr1 + rs1;

        #pragma unroll
        for (int nt = 0; nt < 8; nt++) {
            o[nt][0] *= cr0; o[nt][1] *= cr0;
            o[nt][2] *= cr1; o[nt][3] *= cr1;
        }

        // O += P @ V : S C-frag doubles as PV A-frag
        #pragma unroll
        for (int kg = 0; kg < 4; kg++) {
            float h00 = bf_hi(s[2*kg][0]),   h01 = bf_hi(s[2*kg][1]);
            float h02 = bf_hi(s[2*kg][2]),   h03 = bf_hi(s[2*kg][3]);
            float h10 = bf_hi(s[2*kg+1][0]), h11 = bf_hi(s[2*kg+1][1]);
            float h12 = bf_hi(s[2*kg+1][2]), h13 = bf_hi(s[2*kg+1][3]);
            uint32_t pah[4] = {
                pack_bf2(h00, h01), pack_bf2(h02, h03),
                pack_bf2(h10, h11), pack_bf2(h12, h13) };
            uint32_t pal[4] = {
                pack_bf2(s[2*kg][0]-h00,   s[2*kg][1]-h01),
                pack_bf2(s[2*kg][2]-h02,   s[2*kg][3]-h03),
                pack_bf2(s[2*kg+1][0]-h10, s[2*kg+1][1]-h11),
                pack_bf2(s[2*kg+1][2]-h12, s[2*kg+1][3]-h13) };
            const int kw = kg*8 + lk;
            #pragma unroll
            for (int nt = 0; nt < 8; nt++) {
                const int n = nt*8 + l4;
                uint32_t bh2[2] = { Vh[kw*72 + n], Vh[(kw+4)*72 + n] };
                uint32_t bl2[2] = { Vl[kw*72 + n], Vl[(kw+4)*72 + n] };
                mma16(o[nt], pah, bh2);
                mma16(o[nt], pal, bh2);
                mma16(o[nt], pah, bl2);
            }
        }
    }

    // Normalize + write split-packed planes for proj
    const int b = bh >> 4;
    const int h = bh & 15;
    const float inv0 = 1.f / l_i[0];
    const float inv1 = 1.f / l_i[1];
    const size_t m0r = (size_t)(b*SEQ + q0 + r0);
    #pragma unroll
    for (int nt = 0; nt < 8; nt++) {
        const int w = h*32 + nt*4 + lk;
        float v0 = o[nt][0]*inv0, v1 = o[nt][1]*inv0;
        float h0 = bf_hi(v0), h1 = bf_hi(v1);
        g_Ah[m0r*LDP + w] = pack_bf2(h0, h1);
        g_Al[m0r*LDP + w] = pack_bf2(v0 - h0, v1 - h1);
        float v2 = o[nt][2]*inv1, v3 = o[nt][3]*inv1;
        float h2 = bf_hi(v2), h3 = bf_hi(v3);
        g_Ah[(m0r+8)*LDP + w] = pack_bf2(h2, h3);
        g_Al[(m0r+8)*LDP + w] = pack_bf2(v2 - h2, v3 - h3);
    }
}

// ---------------------------------------------------------------------------
// Output projection: d_out = A @ Wo^T + bo  (A = split-packed planes)
// ---------------------------------------------------------------------------
__global__ void __launch_bounds__(256, 2) proj_kernel(
    const float* __restrict__ bo, float* __restrict__ out)
{
    extern __shared__ uint32_t sm[];

    const int m0 = blockIdx.x * 128;
    const int n0 = blockIdx.y * 128;

    float acc[4][4][4];
    #pragma unroll
    for (int i = 0; i < 4; i++)
        #pragma unroll
        for (int j = 0; j < 4; j++)
            #pragma unroll
            for (int c = 0; c < 4; c++) acc[i][j][c] = 0.f;

    mma_gemm_pl(g_Ah, g_Al, g_Wh[3], g_Wl[3], m0, n0, acc, sm);

    const int lane = threadIdx.x & 31;
    const int warp = threadIdx.x >> 5;
    const int wm = (warp >> 2) * 64;
    const int wn = (warp & 3) * 32;

    #pragma unroll
    for (int mt = 0; mt < 4; mt++) {
        #pragma unroll
        for (int half = 0; half < 2; half++) {
            const int row = m0 + wm + mt*16 + (lane >> 2) + half*8;
            #pragma unroll
            for (int nt = 0; nt < 4; nt++) {
                const int col = n0 + wn + nt*8 + 2*(lane & 3);
                float v0 = acc[mt][nt][half*2+0] + bo[col];
                float v1 = acc[mt][nt][half*2+1] + bo[col+1];
                *(float2*)(out + (size_t)row * D_MODEL + col) = make_float2(v0, v1);
            }
        }
    }
}

extern "C" void kernel_launch(void* const* d_in, const int* in_sizes, int n_in,
                              void* d_out, int out_size)
{
    const float* x  = (const float*)d_in[0];
    const float* Wq = (const float*)d_in[1];
    const float* bq = (const float*)d_in[2];
    const float* Wk = (const float*)d_in[3];
    const float* bk = (const float*)d_in[4];
    const float* Wv = (const float*)d_in[5];
    const float* bv = (const float*)d_in[6];
    const float* Wo = (const float*)d_in[7];
    const float* bo = (const float*)d_in[8];
    float* out = (float*)d_out;

    const int gsmem = 2 * 4 * 128 * 16 * 4;   // 65536 B
    cudaFuncSetAttribute(qkv_kernel,
                         cudaFuncAttributeMaxDynamicSharedMemorySize, gsmem);
    cudaFuncSetAttribute(proj_kernel,
                         cudaFuncAttributeMaxDynamicSharedMemorySize, gsmem);

    convert_kernel<<<dim3(1024, 8), 256>>>(x, Wq, Wk, Wv, Wo);
    qkv_kernel<<<dim3(32, 24), 256, gsmem>>>(bq, bk, bv);
    flash_kernel<<<dim3(SEQ/128, BATCH*NHEAD), 256>>>();
    proj_kernel<<<dim3(32, 8), 256, gsmem>>>(bo, out);
}

// round 6
// speedup vs baseline: 2.2107x; 1.0408x over previous
#include <cuda_runtime.h>
#include <cuda_bf16.h>
#include <cstdint>

#define D_MODEL 1024
#define NHEAD 16
#define HEAD_DIM 64
#define BATCH 2
#define SEQ 2048
#define MTOT (BATCH*SEQ)
#define LDP 512              // plane row stride in words (D_MODEL/2)

// ---------------- scratch (no allocation allowed) -------------------------
__device__ uint32_t g_xh[MTOT*LDP], g_xl[MTOT*LDP];             // x planes
__device__ uint32_t g_Wh[4][D_MODEL*LDP], g_Wl[4][D_MODEL*LDP]; // Wq,Wk,Wv,Wo
__device__ uint32_t g_Qh[32*SEQ*32], g_Ql[32*SEQ*32];           // [bh][tok][32w]
__device__ uint32_t g_Kh[32*SEQ*32], g_Kl[32*SEQ*32];
__device__ uint32_t g_Vh[32*HEAD_DIM*(SEQ/2)];                  // [bh][d][tokpair]
__device__ uint32_t g_Vl[32*HEAD_DIM*(SEQ/2)];
__device__ uint32_t g_Ah[MTOT*LDP], g_Al[MTOT*LDP];             // attn out planes

// ---------------- helpers -------------------------------------------------
__device__ __forceinline__ float bf_hi(float x) {
    uint32_t u = __float_as_uint(x);
    uint32_t hb = (u + 0x7fffu + ((u >> 16) & 1u)) & 0xffff0000u;
    return __uint_as_float(hb);
}
__device__ __forceinline__ uint32_t pack_bf2(float e0, float e1) {
    uint32_t r;
    asm("cvt.rn.bf16x2.f32 %0, %1, %2;" : "=r"(r) : "f"(e1), "f"(e0));
    return r;
}
__device__ __forceinline__ void mma16(float (&d)[4], const uint32_t (&a)[4],
                                      const uint32_t (&b)[2]) {
    asm volatile(
        "mma.sync.aligned.m16n8k16.row.col.f32.bf16.bf16.f32 "
        "{%0,%1,%2,%3}, {%4,%5,%6,%7}, {%8,%9}, {%0,%1,%2,%3};"
        : "+f"(d[0]), "+f"(d[1]), "+f"(d[2]), "+f"(d[3])
        : "r"(a[0]), "r"(a[1]), "r"(a[2]), "r"(a[3]),
          "r"(b[0]), "r"(b[1]));
}
__device__ __forceinline__ void ldsm4(uint32_t (&r)[4], uint32_t saddr) {
    asm volatile("ldmatrix.sync.aligned.m8n8.x4.shared.b16 {%0,%1,%2,%3}, [%4];"
                 : "=r"(r[0]), "=r"(r[1]), "=r"(r[2]), "=r"(r[3]) : "r"(saddr));
}

// ---------------------------------------------------------------------------
// Pre-conversion: fp32 -> packed bf16x2 hi/lo planes.
// blockIdx.y: 0..3 = quarters of x, 4..7 = Wq,Wk,Wv,Wo.
// ---------------------------------------------------------------------------
__global__ void __launch_bounds__(256) convert_kernel(
    const float* __restrict__ x,
    const float* __restrict__ Wq, const float* __restrict__ Wk,
    const float* __restrict__ Wv, const float* __restrict__ Wo)
{
    const int y = blockIdx.y;
    const float* src;
    uint32_t *dh, *dl;
    if (y < 4) { src = x + (size_t)y * 1048576; dh = g_xh + (size_t)y*524288; dl = g_xl + (size_t)y*524288; }
    else {
        src = (y == 4) ? Wq : (y == 5) ? Wk : (y == 6) ? Wv : Wo;
        dh = g_Wh[y-4]; dl = g_Wl[y-4];
    }
    const int idx = blockIdx.x * 256 + threadIdx.x;      // 1024 blocks
    float4 v = ((const float4*)src)[idx];
    float h0 = bf_hi(v.x), h1 = bf_hi(v.y), h2 = bf_hi(v.z), h3 = bf_hi(v.w);
    ((uint2*)dh)[idx] = make_uint2(pack_bf2(h0, h1), pack_bf2(h2, h3));
    ((uint2*)dl)[idx] = make_uint2(pack_bf2(v.x-h0, v.y-h1), pack_bf2(v.z-h2, v.w-h3));
}

// ---------------------------------------------------------------------------
// bf16 2-split GEMM core on packed planes. Tile 128x128, K=1024, KSTG=32.
// 3-stage cp.async pipeline; fragments via ldmatrix.x4; chunk swizzle
// phys = chunk ^ ((row>>1)&3). Smem: 3 bufs x 32 KB = 96 KB dynamic.
// ---------------------------------------------------------------------------
#define NS (D_MODEL/32)

__device__ __forceinline__ void mma_gemm_pl(
    const uint32_t* __restrict__ Aph, const uint32_t* __restrict__ Apl,
    const uint32_t* __restrict__ Bph, const uint32_t* __restrict__ Bpl,
    int m0, int n0, float (&acc)[4][4][4], uint32_t* sm)
{
    const int tid  = threadIdx.x;
    const int lane = tid & 31;
    const int warp = tid >> 5;
    const int wm   = (warp >> 2) * 64;
    const int wn   = (warp & 3) * 32;

    uint32_t sbase = (uint32_t)__cvta_generic_to_shared(sm);

    const int arr = tid >> 6, u = tid & 63;
    const uint32_t* gp = (arr == 0) ? Aph : (arr == 1) ? Apl
                        : (arr == 2) ? Bph : Bpl;
    const int rbase = (arr < 2) ? m0 : n0;
    const int uph   = (u >> 1) & 3;

    #define ISSUE(S, BUF) do {                                               \
        _Pragma("unroll")                                                    \
        for (int c = 0; c < 8; c++) {                                        \
            const int row   = u + 64*(c>>2);                                 \
            const int chunk = c & 3;                                         \
            const int phys  = chunk ^ uph;                                   \
            uint32_t daddr = sbase + (((BUF)*8192 + arr*2048 + row*16 + phys*4) << 2); \
            const uint32_t* sp = gp + (size_t)(rbase + row)*LDP + (S)*16 + chunk*4; \
            asm volatile("cp.async.cg.shared.global [%0], [%1], 16;"         \
                         :: "r"(daddr), "l"(sp));                            \
        }                                                                    \
        asm volatile("cp.async.commit_group;");                              \
    } while (0)

    ISSUE(0, 0);
    ISSUE(1, 1);

    #pragma unroll 1
    for (int s = 0; s < NS; s++) {
        if (s + 2 < NS) {
            ISSUE(s + 2, (s + 2) % 3);
            asm volatile("cp.async.wait_group 2;");
        } else if (s + 1 < NS) {
            asm volatile("cp.async.wait_group 1;");
        } else {
            asm volatile("cp.async.wait_group 0;");
        }
        __syncthreads();

        const uint32_t bb = sbase + (((s % 3)*8192) << 2);
        #pragma unroll
        for (int kb = 0; kb < 2; kb++) {
            uint32_t ah[4][4], al[4][4];
            #pragma unroll
            for (int mt = 0; mt < 4; mt++) {
                const int row   = wm + mt*16 + (lane & 15);
                const int chunk = kb*2 + (lane >> 4);
                const int phys  = chunk ^ ((row >> 1) & 3);
                const uint32_t ad = bb + ((row*16 + phys*4) << 2);
                ldsm4(ah[mt], ad);
                ldsm4(al[mt], ad + (2048u << 2));
            }
            #pragma unroll
            for (int np = 0; np < 2; np++) {
                const int row   = wn + np*16 + (lane & 7) + ((lane & 16) ? 8 : 0);
                const int chunk = kb*2 + ((lane >> 3) & 1);
                const int phys  = chunk ^ ((row >> 1) & 3);
                const uint32_t bd = bb + ((2*2048 + row*16 + phys*4) << 2);
                uint32_t bh4[4], bl4[4];
                ldsm4(bh4, bd);
                ldsm4(bl4, bd + (2048u << 2));
                uint32_t b0h[2] = {bh4[0], bh4[1]}, b1h[2] = {bh4[2], bh4[3]};
                uint32_t b0l[2] = {bl4[0], bl4[1]}, b1l[2] = {bl4[2], bl4[3]};
                #pragma unroll
                for (int mt = 0; mt < 4; mt++) {
                    mma16(acc[mt][2*np],   ah[mt], b0h);
                    mma16(acc[mt][2*np],   al[mt], b0h);
                    mma16(acc[mt][2*np],   ah[mt], b0l);
                    mma16(acc[mt][2*np+1], ah[mt], b1h);
                    mma16(acc[mt][2*np+1], al[mt], b1h);
                    mma16(acc[mt][2*np+1], ah[mt], b1l);
                }
            }
        }
        __syncthreads();
    }
    #undef ISSUE
}

// ---------------------------------------------------------------------------
// Fused QKV projection. blockIdx.y: 0-7 Q, 8-15 K, 16-23 V.
// Q/K write split-packed planes [bh][tok][w]; V writes TRANSPOSED split
// planes [bh][d][tokpair] (rows paired via shfl_xor 4).
// ---------------------------------------------------------------------------
__global__ void __launch_bounds__(256, 2) qkv_kernel(
    const float* __restrict__ bq, const float* __restrict__ bk,
    const float* __restrict__ bv)
{
    extern __shared__ uint32_t sm[];

    const int m0    = blockIdx.x * 128;
    const int tnn   = blockIdx.y;
    const int which = tnn >> 3;
    const int n0    = (tnn & 7) * 128;
    const float* bias = (which == 0) ? bq : ((which == 1) ? bk : bv);

    float acc[4][4][4];
    #pragma unroll
    for (int i = 0; i < 4; i++)
        #pragma unroll
        for (int j = 0; j < 4; j++)
            #pragma unroll
            for (int c = 0; c < 4; c++) acc[i][j][c] = 0.f;

    mma_gemm_pl(g_xh, g_xl, g_Wh[which], g_Wl[which], m0, n0, acc, sm);

    const int lane = threadIdx.x & 31;
    const int warp = threadIdx.x >> 5;
    const int wm = (warp >> 2) * 64;
    const int wn = (warp & 3) * 32;
    const bool evenrow = ((lane >> 2) & 1) == 0;

    #pragma unroll
    for (int mt = 0; mt < 4; mt++) {
        #pragma unroll
        for (int half = 0; half < 2; half++) {
            const int row = m0 + wm + mt*16 + (lane >> 2) + half*8;
            const int b   = row >> 11;
            const int tok = row & 2047;
            #pragma unroll
            for (int nt = 0; nt < 4; nt++) {
                const int col = n0 + wn + nt*8 + 2*(lane & 3);
                float v0 = acc[mt][nt][half*2+0] + bias[col];
                float v1 = acc[mt][nt][half*2+1] + bias[col+1];
                const int h = col >> 6, d = col & 63;
                if (which == 2) {
                    // partner (xor 4) holds row+1 (same cols)
                    float p0 = __shfl_xor_sync(0xffffffffu, v0, 4);
                    float p1 = __shfl_xor_sync(0xffffffffu, v1, 4);
                    if (evenrow) {
                        const size_t idx0 =
                            ((size_t)(b*NHEAD + h)*HEAD_DIM + d)*(SEQ/2) + (tok >> 1);
                        float h0 = bf_hi(v0), hp0 = bf_hi(p0);
                        g_Vh[idx0] = pack_bf2(h0, hp0);
                        g_Vl[idx0] = pack_bf2(v0 - h0, p0 - hp0);
                        float h1 = bf_hi(v1), hp1 = bf_hi(p1);
                        g_Vh[idx0 + (SEQ/2)] = pack_bf2(h1, hp1);
                        g_Vl[idx0 + (SEQ/2)] = pack_bf2(v1 - h1, p1 - hp1);
                    }
                } else {
                    if (which == 0) { v0 = (2.f*v0 - 1.f)*0.125f; v1 = (2.f*v1 - 1.f)*0.125f; }
                    else            { v0 = 2.f*v0 - 1.f;          v1 = 2.f*v1 - 1.f; }
                    float h0 = bf_hi(v0), h1 = bf_hi(v1);
                    const size_t w = (((size_t)(b*NHEAD + h))*SEQ + tok)*32 + (d >> 1);
                    if (which == 0) {
                        g_Qh[w] = pack_bf2(h0, h1);
                        g_Ql[w] = pack_bf2(v0 - h0, v1 - h1);
                    } else {
                        g_Kh[w] = pack_bf2(h0, h1);
                        g_Kl[w] = pack_bf2(v0 - h0, v1 - h1);
                    }
                }
            }
        }
    }
}

// ---------------------------------------------------------------------------
// Flash attention, bf16 2-split. Br=128, Bc=64. K and V staging are pure
// packed copies -> cp.async double-buffered (prefetch tile t+1 during t).
// Smem per buffer: Kh,Kl,Vh,Vl each 64x36 words -> 2 x 36 KB = 72 KB dynamic.
// ---------------------------------------------------------------------------
__global__ void __launch_bounds__(256, 2) flash_kernel()
{
    extern __shared__ uint32_t fsm[];

    const int bh = blockIdx.y;
    const int q0 = blockIdx.x * 128;
    const uint32_t* Qhp = g_Qh + (size_t)bh * SEQ * 32;
    const uint32_t* Qlp = g_Ql + (size_t)bh * SEQ * 32;
    const uint32_t* Khp = g_Kh + (size_t)bh * SEQ * 32;
    const uint32_t* Klp = g_Kl + (size_t)bh * SEQ * 32;
    const size_t    vbase = (size_t)bh * HEAD_DIM * (SEQ/2);

    const int tid  = threadIdx.x;
    const int lane = tid & 31;
    const int warp = tid >> 5;
    const int l4   = lane >> 2;
    const int lk   = lane & 3;
    const int r0   = warp*16 + l4;

    const uint32_t sb = (uint32_t)__cvta_generic_to_shared(fsm);

    #define FISSUE(T, BUF) do {                                              \
        _Pragma("unroll")                                                    \
        for (int it = 0; it < 8; it++) {                                     \
            const int id  = it*256 + tid;                                    \
            const int pl  = id >> 9;                                         \
            const int rid = id & 511;                                        \
            const int row = rid >> 3, ch = (rid & 7) * 4;                    \
            const uint32_t* src;                                             \
            if      (pl == 0) src = Khp + (size_t)((T)*64 + row)*32 + ch;    \
            else if (pl == 1) src = Klp + (size_t)((T)*64 + row)*32 + ch;    \
            else if (pl == 2) src = g_Vh + vbase + (size_t)row*(SEQ/2) + (T)*32 + ch; \
            else              src = g_Vl + vbase + (size_t)row*(SEQ/2) + (T)*32 + ch; \
            uint32_t dst = sb + (((BUF)*9216 + pl*2304 + row*36 + ch) << 2); \
            asm volatile("cp.async.cg.shared.global [%0], [%1], 16;"         \
                         :: "r"(dst), "l"(src));                             \
        }                                                                    \
        asm volatile("cp.async.commit_group;");                              \
    } while (0)

    // Q fragments directly from packed planes
    uint32_t qh[4][4], ql[4][4];
    {
        const size_t r0w = (size_t)(q0 + r0) * 32;
        const size_t r1w = r0w + 8*32;
        #pragma unroll
        for (int kg = 0; kg < 4; kg++) {
            const int w = kg*8 + lk;
            qh[kg][0] = Qhp[r0w + w];     qh[kg][1] = Qhp[r1w + w];
            qh[kg][2] = Qhp[r0w + w + 4]; qh[kg][3] = Qhp[r1w + w + 4];
            ql[kg][0] = Qlp[r0w + w];     ql[kg][1] = Qlp[r1w + w];
            ql[kg][2] = Qlp[r0w + w + 4]; ql[kg][3] = Qlp[r1w + w + 4];
        }
    }

    float m_i[2] = {-1e30f, -1e30f};
    float l_i[2] = {0.f, 0.f};
    float o[8][4];
    #pragma unroll
    for (int nt = 0; nt < 8; nt++)
        #pragma unroll
        for (int c = 0; c < 4; c++) o[nt][c] = 0.f;

    FISSUE(0, 0);

    int buf = 0;
    #pragma unroll 1
    for (int t = 0; t < SEQ/64; t++) {
        if (t + 1 < SEQ/64) {
            FISSUE(t + 1, buf ^ 1);
            asm volatile("cp.async.wait_group 1;");
        } else {
            asm volatile("cp.async.wait_group 0;");
        }
        __syncthreads();

        const uint32_t* Ksh = fsm + buf*9216;
        const uint32_t* Ksl = Ksh + 2304;
        const uint32_t* Vsh = Ksh + 4608;
        const uint32_t* Vsl = Ksh + 6912;

        // S = Qb @ Kb^T (3-term)
        float s[8][4];
        #pragma unroll
        for (int nt = 0; nt < 8; nt++)
            #pragma unroll
            for (int c = 0; c < 4; c++) s[nt][c] = 0.f;

        #pragma unroll
        for (int kg = 0; kg < 4; kg++) {
            const int kw = kg*8 + lk;
            #pragma unroll
            for (int nt = 0; nt < 8; nt++) {
                const int n = nt*8 + l4;
                uint32_t bh2[2] = { Ksh[n*36 + kw], Ksh[n*36 + kw + 4] };
                uint32_t bl2[2] = { Ksl[n*36 + kw], Ksl[n*36 + kw + 4] };
                mma16(s[nt], qh[kg], bh2);
                mma16(s[nt], ql[kg], bh2);
                mma16(s[nt], qh[kg], bl2);
            }
        }

        // Online softmax
        float mx0 = -1e30f, mx1 = -1e30f;
        #pragma unroll
        for (int nt = 0; nt < 8; nt++) {
            mx0 = fmaxf(mx0, fmaxf(s[nt][0], s[nt][1]));
            mx1 = fmaxf(mx1, fmaxf(s[nt][2], s[nt][3]));
        }
        mx0 = fmaxf(mx0, __shfl_xor_sync(0xffffffffu, mx0, 1));
        mx0 = fmaxf(mx0, __shfl_xor_sync(0xffffffffu, mx0, 2));
        mx1 = fmaxf(mx1, __shfl_xor_sync(0xffffffffu, mx1, 1));
        mx1 = fmaxf(mx1, __shfl_xor_sync(0xffffffffu, mx1, 2));

        const float nm0 = fmaxf(m_i[0], mx0);
        const float nm1 = fmaxf(m_i[1], mx1);
        const float cr0 = __expf(m_i[0] - nm0);
        const float cr1 = __expf(m_i[1] - nm1);
        m_i[0] = nm0; m_i[1] = nm1;

        float rs0 = 0.f, rs1 = 0.f;
        #pragma unroll
        for (int nt = 0; nt < 8; nt++) {
            s[nt][0] = __expf(s[nt][0] - nm0);
            s[nt][1] = __expf(s[nt][1] - nm0);
            s[nt][2] = __expf(s[nt][2] - nm1);
            s[nt][3] = __expf(s[nt][3] - nm1);
            rs0 += s[nt][0] + s[nt][1];
            rs1 += s[nt][2] + s[nt][3];
        }
        rs0 += __shfl_xor_sync(0xffffffffu, rs0, 1);
        rs0 += __shfl_xor_sync(0xffffffffu, rs0, 2);
        rs1 += __shfl_xor_sync(0xffffffffu, rs1, 1);
        rs1 += __shfl_xor_sync(0xffffffffu, rs1, 2);
        l_i[0] = l_i[0]*cr0 + rs0;
        l_i[1] = l_i[1]*cr1 + rs1;

        #pragma unroll
        for (int nt = 0; nt < 8; nt++) {
            o[nt][0] *= cr0; o[nt][1] *= cr0;
            o[nt][2] *= cr1; o[nt][3] *= cr1;
        }

        // O += P @ V : S C-frag doubles as PV A-frag
        #pragma unroll
        for (int kg = 0; kg < 4; kg++) {
            float h00 = bf_hi(s[2*kg][0]),   h01 = bf_hi(s[2*kg][1]);
            float h02 = bf_hi(s[2*kg][2]),   h03 = bf_hi(s[2*kg][3]);
            float h10 = bf_hi(s[2*kg+1][0]), h11 = bf_hi(s[2*kg+1][1]);
            float h12 = bf_hi(s[2*kg+1][2]), h13 = bf_hi(s[2*kg+1][3]);
            uint32_t pah[4] = {
                pack_bf2(h00, h01), pack_bf2(h02, h03),
                pack_bf2(h10, h11), pack_bf2(h12, h13) };
            uint32_t pal[4] = {
                pack_bf2(s[2*kg][0]-h00,   s[2*kg][1]-h01),
                pack_bf2(s[2*kg][2]-h02,   s[2*kg][3]-h03),
                pack_bf2(s[2*kg+1][0]-h10, s[2*kg+1][1]-h11),
                pack_bf2(s[2*kg+1][2]-h12, s[2*kg+1][3]-h13) };
            const int kw = kg*8 + lk;
            #pragma unroll
            for (int nt = 0; nt < 8; nt++) {
                const int n = nt*8 + l4;
                uint32_t bh2[2] = { Vsh[n*36 + kw], Vsh[n*36 + kw + 4] };
                uint32_t bl2[2] = { Vsl[n*36 + kw], Vsl[n*36 + kw + 4] };
                mma16(o[nt], pah, bh2);
                mma16(o[nt], pal, bh2);
                mma16(o[nt], pah, bl2);
            }
        }
        __syncthreads();
        buf ^= 1;
    }
    #undef FISSUE

    // Normalize + write split-packed planes for proj
    const int b = bh >> 4;
    const int h = bh & 15;
    const float inv0 = 1.f / l_i[0];
    const float inv1 = 1.f / l_i[1];
    const size_t m0r = (size_t)(b*SEQ + q0 + r0);
    #pragma unroll
    for (int nt = 0; nt < 8; nt++) {
        const int w = h*32 + nt*4 + lk;
        float v0 = o[nt][0]*inv0, v1 = o[nt][1]*inv0;
        float h0 = bf_hi(v0), h1 = bf_hi(v1);
        g_Ah[m0r*LDP + w] = pack_bf2(h0, h1);
        g_Al[m0r*LDP + w] = pack_bf2(v0 - h0, v1 - h1);
        float v2 = o[nt][2]*inv1, v3 = o[nt][3]*inv1;
        float h2 = bf_hi(v2), h3 = bf_hi(v3);
        g_Ah[(m0r+8)*LDP + w] = pack_bf2(h2, h3);
        g_Al[(m0r+8)*LDP + w] = pack_bf2(v2 - h2, v3 - h3);
    }
}

// ---------------------------------------------------------------------------
// Output projection: d_out = A @ Wo^T + bo  (A = split-packed planes)
// ---------------------------------------------------------------------------
__global__ void __launch_bounds__(256, 2) proj_kernel(
    const float* __restrict__ bo, float* __restrict__ out)
{
    extern __shared__ uint32_t sm[];

    const int m0 = blockIdx.x * 128;
    const int n0 = blockIdx.y * 128;

    float acc[4][4][4];
    #pragma unroll
    for (int i = 0; i < 4; i++)
        #pragma unroll
        for (int j = 0; j < 4; j++)
            #pragma unroll
            for (int c = 0; c < 4; c++) acc[i][j][c] = 0.f;

    mma_gemm_pl(g_Ah, g_Al, g_Wh[3], g_Wl[3], m0, n0, acc, sm);

    const int lane = threadIdx.x & 31;
    const int warp = threadIdx.x >> 5;
    const int wm = (warp >> 2) * 64;
    const int wn = (warp & 3) * 32;

    #pragma unroll
    for (int mt = 0; mt < 4; mt++) {
        #pragma unroll
        for (int half = 0; half < 2; half++) {
            const int row = m0 + wm + mt*16 + (lane >> 2) + half*8;
            #pragma unroll
            for (int nt = 0; nt < 4; nt++) {
                const int col = n0 + wn + nt*8 + 2*(lane & 3);
                float v0 = acc[mt][nt][half*2+0] + bo[col];
                float v1 = acc[mt][nt][half*2+1] + bo[col+1];
                *(float2*)(out + (size_t)row * D_MODEL + col) = make_float2(v0, v1);
            }
        }
    }
}

extern "C" void kernel_launch(void* const* d_in, const int* in_sizes, int n_in,
                              void* d_out, int out_size)
{
    const float* x  = (const float*)d_in[0];
    const float* Wq = (const float*)d_in[1];
    const float* bq = (const float*)d_in[2];
    const float* Wk = (const float*)d_in[3];
    const float* bk = (const float*)d_in[4];
    const float* Wv = (const float*)d_in[5];
    const float* bv = (const float*)d_in[6];
    const float* Wo = (const float*)d_in[7];
    const float* bo = (const float*)d_in[8];
    float* out = (float*)d_out;

    const int gsmem = 3 * 4 * 128 * 16 * 4;   // 98304 B (3-stage)
    const int fsmem = 2 * 4 * 2304 * 4;       // 73728 B (double buffer)
    cudaFuncSetAttribute(qkv_kernel,
                         cudaFuncAttributeMaxDynamicSharedMemorySize, gsmem);
    cudaFuncSetAttribute(proj_kernel,
                         cudaFuncAttributeMaxDynamicSharedMemorySize, gsmem);
    cudaFuncSetAttribute(flash_kernel,
                         cudaFuncAttributeMaxDynamicSharedMemorySize, fsmem);

    convert_kernel<<<dim3(1024, 8), 256>>>(x, Wq, Wk, Wv, Wo);
    qkv_kernel<<<dim3(32, 24), 256, gsmem>>>(bq, bk, bv);
    flash_kernel<<<dim3(SEQ/128, BATCH*NHEAD), 256, fsmem>>>();
    proj_kernel<<<dim3(32, 8), 256, gsmem>>>(bo, out);
}

// round 7
// speedup vs baseline: 2.2128x; 1.0010x over previous
#include <cuda_runtime.h>
#include <cuda_bf16.h>
#include <cstdint>

#define D_MODEL 1024
#define NHEAD 16
#define HEAD_DIM 64
#define BATCH 2
#define SEQ 2048
#define MTOT (BATCH*SEQ)
#define LDP 512              // plane row stride in words (D_MODEL/2)

// ---------------- scratch (no allocation allowed) -------------------------
__device__ uint32_t g_xh[MTOT*LDP], g_xl[MTOT*LDP];             // x planes
__device__ uint32_t g_Wh[4][D_MODEL*LDP], g_Wl[4][D_MODEL*LDP]; // Wq,Wk,Wv,Wo
__device__ uint32_t g_Qh[32*SEQ*32], g_Ql[32*SEQ*32];           // [bh][tok][32w]
__device__ uint32_t g_Kh[32*SEQ*32], g_Kl[32*SEQ*32];
__device__ uint32_t g_Vh[32*HEAD_DIM*(SEQ/2)];                  // [bh][d][tokpair]
__device__ uint32_t g_Vl[32*HEAD_DIM*(SEQ/2)];
__device__ uint32_t g_Ah[MTOT*LDP], g_Al[MTOT*LDP];             // attn out planes

// ---------------- helpers -------------------------------------------------
__device__ __forceinline__ float bf_hi(float x) {
    uint32_t u = __float_as_uint(x);
    uint32_t hb = (u + 0x7fffu + ((u >> 16) & 1u)) & 0xffff0000u;
    return __uint_as_float(hb);
}
__device__ __forceinline__ uint32_t pack_bf2(float e0, float e1) {
    uint32_t r;
    asm("cvt.rn.bf16x2.f32 %0, %1, %2;" : "=r"(r) : "f"(e1), "f"(e0));
    return r;
}
__device__ __forceinline__ void mma16(float (&d)[4], const uint32_t (&a)[4],
                                      const uint32_t (&b)[2]) {
    asm volatile(
        "mma.sync.aligned.m16n8k16.row.col.f32.bf16.bf16.f32 "
        "{%0,%1,%2,%3}, {%4,%5,%6,%7}, {%8,%9}, {%0,%1,%2,%3};"
        : "+f"(d[0]), "+f"(d[1]), "+f"(d[2]), "+f"(d[3])
        : "r"(a[0]), "r"(a[1]), "r"(a[2]), "r"(a[3]),
          "r"(b[0]), "r"(b[1]));
}
__device__ __forceinline__ void ldsm4(uint32_t (&r)[4], uint32_t saddr) {
    asm volatile("ldmatrix.sync.aligned.m8n8.x4.shared.b16 {%0,%1,%2,%3}, [%4];"
                 : "=r"(r[0]), "=r"(r[1]), "=r"(r[2]), "=r"(r[3]) : "r"(saddr));
}

// ---------------------------------------------------------------------------
// Pre-conversion: fp32 -> packed bf16x2 hi/lo planes.
// ---------------------------------------------------------------------------
__global__ void __launch_bounds__(256) convert_kernel(
    const float* __restrict__ x,
    const float* __restrict__ Wq, const float* __restrict__ Wk,
    const float* __restrict__ Wv, const float* __restrict__ Wo)
{
    const int y = blockIdx.y;
    const float* src;
    uint32_t *dh, *dl;
    if (y < 4) { src = x + (size_t)y * 1048576; dh = g_xh + (size_t)y*524288; dl = g_xl + (size_t)y*524288; }
    else {
        src = (y == 4) ? Wq : (y == 5) ? Wk : (y == 6) ? Wv : Wo;
        dh = g_Wh[y-4]; dl = g_Wl[y-4];
    }
    const int idx = blockIdx.x * 256 + threadIdx.x;
    float4 v = ((const float4*)src)[idx];
    float h0 = bf_hi(v.x), h1 = bf_hi(v.y), h2 = bf_hi(v.z), h3 = bf_hi(v.w);
    ((uint2*)dh)[idx] = make_uint2(pack_bf2(h0, h1), pack_bf2(h2, h3));
    ((uint2*)dl)[idx] = make_uint2(pack_bf2(v.x-h0, v.y-h1), pack_bf2(v.z-h2, v.w-h3));
}

// ---------------------------------------------------------------------------
// bf16 2-split GEMM core. Tile 128x128, K=1024, KSTG=32, 3-stage cp.async.
// MMA issue reordered: term (hh/lh/hl) OUTER so consecutive HMMAs hit
// different accumulators (reuse distance 8). Per-acc term order unchanged.
// ---------------------------------------------------------------------------
#define NS (D_MODEL/32)

__device__ __forceinline__ void mma_gemm_pl(
    const uint32_t* __restrict__ Aph, const uint32_t* __restrict__ Apl,
    const uint32_t* __restrict__ Bph, const uint32_t* __restrict__ Bpl,
    int m0, int n0, float (&acc)[4][4][4], uint32_t* sm)
{
    const int tid  = threadIdx.x;
    const int lane = tid & 31;
    const int warp = tid >> 5;
    const int wm   = (warp >> 2) * 64;
    const int wn   = (warp & 3) * 32;

    uint32_t sbase = (uint32_t)__cvta_generic_to_shared(sm);

    const int arr = tid >> 6, u = tid & 63;
    const uint32_t* gp = (arr == 0) ? Aph : (arr == 1) ? Apl
                        : (arr == 2) ? Bph : Bpl;
    const int rbase = (arr < 2) ? m0 : n0;
    const int uph   = (u >> 1) & 3;

    #define ISSUE(S, BUF) do {                                               \
        _Pragma("unroll")                                                    \
        for (int c = 0; c < 8; c++) {                                        \
            const int row   = u + 64*(c>>2);                                 \
            const int chunk = c & 3;                                         \
            const int phys  = chunk ^ uph;                                   \
            uint32_t daddr = sbase + (((BUF)*8192 + arr*2048 + row*16 + phys*4) << 2); \
            const uint32_t* sp = gp + (size_t)(rbase + row)*LDP + (S)*16 + chunk*4; \
            asm volatile("cp.async.cg.shared.global [%0], [%1], 16;"         \
                         :: "r"(daddr), "l"(sp));                            \
        }                                                                    \
        asm volatile("cp.async.commit_group;");                              \
    } while (0)

    ISSUE(0, 0);
    ISSUE(1, 1);

    #pragma unroll 1
    for (int s = 0; s < NS; s++) {
        if (s + 2 < NS) {
            ISSUE(s + 2, (s + 2) % 3);
            asm volatile("cp.async.wait_group 2;");
        } else if (s + 1 < NS) {
            asm volatile("cp.async.wait_group 1;");
        } else {
            asm volatile("cp.async.wait_group 0;");
        }
        __syncthreads();

        const uint32_t bb = sbase + (((s % 3)*8192) << 2);
        #pragma unroll
        for (int kb = 0; kb < 2; kb++) {
            uint32_t ah[4][4], al[4][4];
            #pragma unroll
            for (int mt = 0; mt < 4; mt++) {
                const int row   = wm + mt*16 + (lane & 15);
                const int chunk = kb*2 + (lane >> 4);
                const int phys  = chunk ^ ((row >> 1) & 3);
                const uint32_t ad = bb + ((row*16 + phys*4) << 2);
                ldsm4(ah[mt], ad);
                ldsm4(al[mt], ad + (2048u << 2));
            }
            #pragma unroll
            for (int np = 0; np < 2; np++) {
                const int row   = wn + np*16 + (lane & 7) + ((lane & 16) ? 8 : 0);
                const int chunk = kb*2 + ((lane >> 3) & 1);
                const int phys  = chunk ^ ((row >> 1) & 3);
                const uint32_t bd = bb + ((2*2048 + row*16 + phys*4) << 2);
                uint32_t bh4[4], bl4[4];
                ldsm4(bh4, bd);
                ldsm4(bl4, bd + (2048u << 2));
                uint32_t b0h[2] = {bh4[0], bh4[1]}, b1h[2] = {bh4[2], bh4[3]};
                uint32_t b0l[2] = {bl4[0], bl4[1]}, b1l[2] = {bl4[2], bl4[3]};
                // term 0: hi*hi (8 independent HMMAs)
                #pragma unroll
                for (int mt = 0; mt < 4; mt++) {
                    mma16(acc[mt][2*np],   ah[mt], b0h);
                    mma16(acc[mt][2*np+1], ah[mt], b1h);
                }
                // term 1: lo*hi
                #pragma unroll
                for (int mt = 0; mt < 4; mt++) {
                    mma16(acc[mt][2*np],   al[mt], b0h);
                    mma16(acc[mt][2*np+1], al[mt], b1h);
                }
                // term 2: hi*lo
                #pragma unroll
                for (int mt = 0; mt < 4; mt++) {
                    mma16(acc[mt][2*np],   ah[mt], b0l);
                    mma16(acc[mt][2*np+1], ah[mt], b1l);
                }
            }
        }
        __syncthreads();
    }
    #undef ISSUE
}

// ---------------------------------------------------------------------------
// Fused QKV projection. blockIdx.y: 0-7 Q, 8-15 K, 16-23 V.
// ---------------------------------------------------------------------------
__global__ void __launch_bounds__(256, 2) qkv_kernel(
    const float* __restrict__ bq, const float* __restrict__ bk,
    const float* __restrict__ bv)
{
    extern __shared__ uint32_t sm[];

    const int m0    = blockIdx.x * 128;
    const int tnn   = blockIdx.y;
    const int which = tnn >> 3;
    const int n0    = (tnn & 7) * 128;
    const float* bias = (which == 0) ? bq : ((which == 1) ? bk : bv);

    float acc[4][4][4];
    #pragma unroll
    for (int i = 0; i < 4; i++)
        #pragma unroll
        for (int j = 0; j < 4; j++)
            #pragma unroll
            for (int c = 0; c < 4; c++) acc[i][j][c] = 0.f;

    mma_gemm_pl(g_xh, g_xl, g_Wh[which], g_Wl[which], m0, n0, acc, sm);

    const int lane = threadIdx.x & 31;
    const int warp = threadIdx.x >> 5;
    const int wm = (warp >> 2) * 64;
    const int wn = (warp & 3) * 32;
    const bool evenrow = ((lane >> 2) & 1) == 0;

    #pragma unroll
    for (int mt = 0; mt < 4; mt++) {
        #pragma unroll
        for (int half = 0; half < 2; half++) {
            const int row = m0 + wm + mt*16 + (lane >> 2) + half*8;
            const int b   = row >> 11;
            const int tok = row & 2047;
            #pragma unroll
            for (int nt = 0; nt < 4; nt++) {
                const int col = n0 + wn + nt*8 + 2*(lane & 3);
                float v0 = acc[mt][nt][half*2+0] + bias[col];
                float v1 = acc[mt][nt][half*2+1] + bias[col+1];
                const int h = col >> 6, d = col & 63;
                if (which == 2) {
                    float p0 = __shfl_xor_sync(0xffffffffu, v0, 4);
                    float p1 = __shfl_xor_sync(0xffffffffu, v1, 4);
                    if (evenrow) {
                        const size_t idx0 =
                            ((size_t)(b*NHEAD + h)*HEAD_DIM + d)*(SEQ/2) + (tok >> 1);
                        float h0 = bf_hi(v0), hp0 = bf_hi(p0);
                        g_Vh[idx0] = pack_bf2(h0, hp0);
                        g_Vl[idx0] = pack_bf2(v0 - h0, p0 - hp0);
                        float h1 = bf_hi(v1), hp1 = bf_hi(p1);
                        g_Vh[idx0 + (SEQ/2)] = pack_bf2(h1, hp1);
                        g_Vl[idx0 + (SEQ/2)] = pack_bf2(v1 - h1, p1 - hp1);
                    }
                } else {
                    if (which == 0) { v0 = (2.f*v0 - 1.f)*0.125f; v1 = (2.f*v1 - 1.f)*0.125f; }
                    else            { v0 = 2.f*v0 - 1.f;          v1 = 2.f*v1 - 1.f; }
                    float h0 = bf_hi(v0), h1 = bf_hi(v1);
                    const size_t w = (((size_t)(b*NHEAD + h))*SEQ + tok)*32 + (d >> 1);
                    if (which == 0) {
                        g_Qh[w] = pack_bf2(h0, h1);
                        g_Ql[w] = pack_bf2(v0 - h0, v1 - h1);
                    } else {
                        g_Kh[w] = pack_bf2(h0, h1);
                        g_Kl[w] = pack_bf2(v0 - h0, v1 - h1);
                    }
                }
            }
        }
    }
}

// ---------------------------------------------------------------------------
// Flash attention, bf16 2-split, cp.async double-buffered K/V copies.
// MMA loops reordered: nt processed in groups of 4 with term outer ->
// accumulator reuse distance 4 (was 1).
// ---------------------------------------------------------------------------
__global__ void __launch_bounds__(256, 2) flash_kernel()
{
    extern __shared__ uint32_t fsm[];

    const int bh = blockIdx.y;
    const int q0 = blockIdx.x * 128;
    const uint32_t* Qhp = g_Qh + (size_t)bh * SEQ * 32;
    const uint32_t* Qlp = g_Ql + (size_t)bh * SEQ * 32;
    const uint32_t* Khp = g_Kh + (size_t)bh * SEQ * 32;
    const uint32_t* Klp = g_Kl + (size_t)bh * SEQ * 32;
    const size_t    vbase = (size_t)bh * HEAD_DIM * (SEQ/2);

    const int tid  = threadIdx.x;
    const int lane = tid & 31;
    const int warp = tid >> 5;
    const int l4   = lane >> 2;
    const int lk   = lane & 3;
    const int r0   = warp*16 + l4;

    const uint32_t sb = (uint32_t)__cvta_generic_to_shared(fsm);

    #define FISSUE(T, BUF) do {                                              \
        _Pragma("unroll")                                                    \
        for (int it = 0; it < 8; it++) {                                     \
            const int id  = it*256 + tid;                                    \
            const int pl  = id >> 9;                                         \
            const int rid = id & 511;                                        \
            const int row = rid >> 3, ch = (rid & 7) * 4;                    \
            const uint32_t* src;                                             \
            if      (pl == 0) src = Khp + (size_t)((T)*64 + row)*32 + ch;    \
            else if (pl == 1) src = Klp + (size_t)((T)*64 + row)*32 + ch;    \
            else if (pl == 2) src = g_Vh + vbase + (size_t)row*(SEQ/2) + (T)*32 + ch; \
            else              src = g_Vl + vbase + (size_t)row*(SEQ/2) + (T)*32 + ch; \
            uint32_t dst = sb + (((BUF)*9216 + pl*2304 + row*36 + ch) << 2); \
            asm volatile("cp.async.cg.shared.global [%0], [%1], 16;"         \
                         :: "r"(dst), "l"(src));                             \
        }                                                                    \
        asm volatile("cp.async.commit_group;");                              \
    } while (0)

    // Q fragments directly from packed planes
    uint32_t qh[4][4], ql[4][4];
    {
        const size_t r0w = (size_t)(q0 + r0) * 32;
        const size_t r1w = r0w + 8*32;
        #pragma unroll
        for (int kg = 0; kg < 4; kg++) {
            const int w = kg*8 + lk;
            qh[kg][0] = Qhp[r0w + w];     qh[kg][1] = Qhp[r1w + w];
            qh[kg][2] = Qhp[r0w + w + 4]; qh[kg][3] = Qhp[r1w + w + 4];
            ql[kg][0] = Qlp[r0w + w];     ql[kg][1] = Qlp[r1w + w];
            ql[kg][2] = Qlp[r0w + w + 4]; ql[kg][3] = Qlp[r1w + w + 4];
        }
    }

    float m_i[2] = {-1e30f, -1e30f};
    float l_i[2] = {0.f, 0.f};
    float o[8][4];
    #pragma unroll
    for (int nt = 0; nt < 8; nt++)
        #pragma unroll
        for (int c = 0; c < 4; c++) o[nt][c] = 0.f;

    FISSUE(0, 0);

    int buf = 0;
    #pragma unroll 1
    for (int t = 0; t < SEQ/64; t++) {
        if (t + 1 < SEQ/64) {
            FISSUE(t + 1, buf ^ 1);
            asm volatile("cp.async.wait_group 1;");
        } else {
            asm volatile("cp.async.wait_group 0;");
        }
        __syncthreads();

        const uint32_t* Ksh = fsm + buf*9216;
        const uint32_t* Ksl = Ksh + 2304;
        const uint32_t* Vsh = Ksh + 4608;
        const uint32_t* Vsl = Ksh + 6912;

        // S = Qb @ Kb^T (3-term, reordered: groups of 4 nt, term outer)
        float s[8][4];
        #pragma unroll
        for (int nt = 0; nt < 8; nt++)
            #pragma unroll
            for (int c = 0; c < 4; c++) s[nt][c] = 0.f;

        #pragma unroll
        for (int kg = 0; kg < 4; kg++) {
            const int kw = kg*8 + lk;
            #pragma unroll
            for (int g = 0; g < 2; g++) {
                uint32_t fh[4][2], fl[4][2];
                #pragma unroll
                for (int j = 0; j < 4; j++) {
                    const int n = (g*4 + j)*8 + l4;
                    fh[j][0] = Ksh[n*36 + kw]; fh[j][1] = Ksh[n*36 + kw + 4];
                    fl[j][0] = Ksl[n*36 + kw]; fl[j][1] = Ksl[n*36 + kw + 4];
                }
                #pragma unroll
                for (int j = 0; j < 4; j++) mma16(s[g*4+j], qh[kg], fh[j]);
                #pragma unroll
                for (int j = 0; j < 4; j++) mma16(s[g*4+j], ql[kg], fh[j]);
                #pragma unroll
                for (int j = 0; j < 4; j++) mma16(s[g*4+j], qh[kg], fl[j]);
            }
        }

        // Online softmax
        float mx0 = -1e30f, mx1 = -1e30f;
        #pragma unroll
        for (int nt = 0; nt < 8; nt++) {
            mx0 = fmaxf(mx0, fmaxf(s[nt][0], s[nt][1]));
            mx1 = fmaxf(mx1, fmaxf(s[nt][2], s[nt][3]));
        }
        mx0 = fmaxf(mx0, __shfl_xor_sync(0xffffffffu, mx0, 1));
        mx0 = fmaxf(mx0, __shfl_xor_sync(0xffffffffu, mx0, 2));
        mx1 = fmaxf(mx1, __shfl_xor_sync(0xffffffffu, mx1, 1));
        mx1 = fmaxf(mx1, __shfl_xor_sync(0xffffffffu, mx1, 2));

        const float nm0 = fmaxf(m_i[0], mx0);
        const float nm1 = fmaxf(m_i[1], mx1);
        const float cr0 = __expf(m_i[0] - nm0);
        const float cr1 = __expf(m_i[1] - nm1);
        m_i[0] = nm0; m_i[1] = nm1;

        float rs0 = 0.f, rs1 = 0.f;
        #pragma unroll
        for (int nt = 0; nt < 8; nt++) {
            s[nt][0] = __expf(s[nt][0] - nm0);
            s[nt][1] = __expf(s[nt][1] - nm0);
            s[nt][2] = __expf(s[nt][2] - nm1);
            s[nt][3] = __expf(s[nt][3] - nm1);
            rs0 += s[nt][0] + s[nt][1];
            rs1 += s[nt][2] + s[nt][3];
        }
        rs0 += __shfl_xor_sync(0xffffffffu, rs0, 1);
        rs0 += __shfl_xor_sync(0xffffffffu, rs0, 2);
        rs1 += __shfl_xor_sync(0xffffffffu, rs1, 1);
        rs1 += __shfl_xor_sync(0xffffffffu, rs1, 2);
        l_i[0] = l_i[0]*cr0 + rs0;
        l_i[1] = l_i[1]*cr1 + rs1;

        #pragma unroll
        for (int nt = 0; nt < 8; nt++) {
            o[nt][0] *= cr0; o[nt][1] *= cr0;
            o[nt][2] *= cr1; o[nt][3] *= cr1;
        }

        // O += P @ V (reordered like S)
        #pragma unroll
        for (int kg = 0; kg < 4; kg++) {
            float h00 = bf_hi(s[2*kg][0]),   h01 = bf_hi(s[2*kg][1]);
            float h02 = bf_hi(s[2*kg][2]),   h03 = bf_hi(s[2*kg][3]);
            float h10 = bf_hi(s[2*kg+1][0]), h11 = bf_hi(s[2*kg+1][1]);
            float h12 = bf_hi(s[2*kg+1][2]), h13 = bf_hi(s[2*kg+1][3]);
            uint32_t pah[4] = {
                pack_bf2(h00, h01), pack_bf2(h02, h03),
                pack_bf2(h10, h11), pack_bf2(h12, h13) };
            uint32_t pal[4] = {
                pack_bf2(s[2*kg][0]-h00,   s[2*kg][1]-h01),
                pack_bf2(s[2*kg][2]-h02,   s[2*kg][3]-h03),
                pack_bf2(s[2*kg+1][0]-h10, s[2*kg+1][1]-h11),
                pack_bf2(s[2*kg+1][2]-h12, s[2*kg+1][3]-h13) };
            const int kw = kg*8 + lk;
            #pragma unroll
            for (int g = 0; g < 2; g++) {
                uint32_t fh[4][2], fl[4][2];
                #pragma unroll
                for (int j = 0; j < 4; j++) {
                    const int n = (g*4 + j)*8 + l4;
                    fh[j][0] = Vsh[n*36 + kw]; fh[j][1] = Vsh[n*36 + kw + 4];
                    fl[j][0] = Vsl[n*36 + kw]; fl[j][1] = Vsl[n*36 + kw + 4];
                }
                #pragma unroll
                for (int j = 0; j < 4; j++) mma16(o[g*4+j], pah, fh[j]);
                #pragma unroll
                for (int j = 0; j < 4; j++) mma16(o[g*4+j], pal, fh[j]);
                #pragma unroll
                for (int j = 0; j < 4; j++) mma16(o[g*4+j], pah, fl[j]);
            }
        }
        __syncthreads();
        buf ^= 1;
    }
    #undef FISSUE

    // Normalize + write split-packed planes for proj
    const int b = bh >> 4;
    const int h = bh & 15;
    const float inv0 = 1.f / l_i[0];
    const float inv1 = 1.f / l_i[1];
    const size_t m0r = (size_t)(b*SEQ + q0 + r0);
    #pragma unroll
    for (int nt = 0; nt < 8; nt++) {
        const int w = h*32 + nt*4 + lk;
        float v0 = o[nt][0]*inv0, v1 = o[nt][1]*inv0;
        float h0 = bf_hi(v0), h1 = bf_hi(v1);
        g_Ah[m0r*LDP + w] = pack_bf2(h0, h1);
        g_Al[m0r*LDP + w] = pack_bf2(v0 - h0, v1 - h1);
        float v2 = o[nt][2]*inv1, v3 = o[nt][3]*inv1;
        float h2 = bf_hi(v2), h3 = bf_hi(v3);
        g_Ah[(m0r+8)*LDP + w] = pack_bf2(h2, h3);
        g_Al[(m0r+8)*LDP + w] = pack_bf2(v2 - h2, v3 - h3);
    }
}

// ---------------------------------------------------------------------------
// Output projection: d_out = A @ Wo^T + bo
// ---------------------------------------------------------------------------
__global__ void __launch_bounds__(256, 2) proj_kernel(
    const float* __restrict__ bo, float* __restrict__ out)
{
    extern __shared__ uint32_t sm[];

    const int m0 = blockIdx.x * 128;
    const int n0 = blockIdx.y * 128;

    float acc[4][4][4];
    #pragma unroll
    for (int i = 0; i < 4; i++)
        #pragma unroll
        for (int j = 0; j < 4; j++)
            #pragma unroll
            for (int c = 0; c < 4; c++) acc[i][j][c] = 0.f;

    mma_gemm_pl(g_Ah, g_Al, g_Wh[3], g_Wl[3], m0, n0, acc, sm);

    const int lane = threadIdx.x & 31;
    const int warp = threadIdx.x >> 5;
    const int wm = (warp >> 2) * 64;
    const int wn = (warp & 3) * 32;

    #pragma unroll
    for (int mt = 0; mt < 4; mt++) {
        #pragma unroll
        for (int half = 0; half < 2; half++) {
            const int row = m0 + wm + mt*16 + (lane >> 2) + half*8;
            #pragma unroll
            for (int nt = 0; nt < 4; nt++) {
                const int col = n0 + wn + nt*8 + 2*(lane & 3);
                float v0 = acc[mt][nt][half*2+0] + bo[col];
                float v1 = acc[mt][nt][half*2+1] + bo[col+1];
                *(float2*)(out + (size_t)row * D_MODEL + col) = make_float2(v0, v1);
            }
        }
    }
}

extern "C" void kernel_launch(void* const* d_in, const int* in_sizes, int n_in,
                              void* d_out, int out_size)
{
    const float* x  = (const float*)d_in[0];
    const float* Wq = (const float*)d_in[1];
    const float* bq = (const float*)d_in[2];
    const float* Wk = (const float*)d_in[3];
    const float* bk = (const float*)d_in[4];
    const float* Wv = (const float*)d_in[5];
    const float* bv = (const float*)d_in[6];
    const float* Wo = (const float*)d_in[7];
    const float* bo = (const float*)d_in[8];
    float* out = (float*)d_out;

    const int gsmem = 3 * 4 * 128 * 16 * 4;   // 98304 B
    const int fsmem = 2 * 4 * 2304 * 4;       // 73728 B
    cudaFuncSetAttribute(qkv_kernel,
                         cudaFuncAttributeMaxDynamicSharedMemorySize, gsmem);
    cudaFuncSetAttribute(proj_kernel,
                         cudaFuncAttributeMaxDynamicSharedMemorySize, gsmem);
    cudaFuncSetAttribute(flash_kernel,
                         cudaFuncAttributeMaxDynamicSharedMemorySize, fsmem);

    convert_kernel<<<dim3(1024, 8), 256>>>(x, Wq, Wk, Wv, Wo);
    qkv_kernel<<<dim3(32, 24), 256, gsmem>>>(bq, bk, bv);
    flash_kernel<<<dim3(SEQ/128, BATCH*NHEAD), 256, fsmem>>>();
    proj_kernel<<<dim3(32, 8), 256, gsmem>>>(bo, out);
}

// round 9
// speedup vs baseline: 2.6308x; 1.1889x over previous
#include <cuda_runtime.h>
#include <cuda_bf16.h>
#include <cstdint>

#define D_MODEL 1024
#define NHEAD 16
#define HEAD_DIM 64
#define BATCH 2
#define SEQ 2048
#define MTOT (BATCH*SEQ)
#define LDP 512              // plane row stride in words (D_MODEL/2)

// ---------------- scratch (no allocation allowed) -------------------------
__device__ uint32_t g_xh[MTOT*LDP], g_xl[MTOT*LDP];             // x planes
__device__ uint32_t g_Wh[4][D_MODEL*LDP], g_Wl[4][D_MODEL*LDP]; // Wq,Wk,Wv,Wo
__device__ uint32_t g_Qh[32*SEQ*32], g_Ql[32*SEQ*32];           // [bh][tok][32w]
__device__ uint32_t g_Kh[32*SEQ*32], g_Kl[32*SEQ*32];
__device__ uint32_t g_Vh[32*HEAD_DIM*(SEQ/2)];                  // [bh][d][tokpair]
__device__ uint32_t g_Vl[32*HEAD_DIM*(SEQ/2)];
__device__ uint32_t g_Ah[MTOT*LDP], g_Al[MTOT*LDP];             // attn out planes

// ---------------- helpers -------------------------------------------------
__device__ __forceinline__ float bf_hi(float x) {
    uint32_t u = __float_as_uint(x);
    uint32_t hb = (u + 0x7fffu + ((u >> 16) & 1u)) & 0xffff0000u;
    return __uint_as_float(hb);
}
__device__ __forceinline__ uint32_t pack_bf2(float e0, float e1) {
    uint32_t r;
    asm("cvt.rn.bf16x2.f32 %0, %1, %2;" : "=r"(r) : "f"(e1), "f"(e0));
    return r;
}
__device__ __forceinline__ void mma16(float (&d)[4], const uint32_t (&a)[4],
                                      const uint32_t (&b)[2]) {
    asm volatile(
        "mma.sync.aligned.m16n8k16.row.col.f32.bf16.bf16.f32 "
        "{%0,%1,%2,%3}, {%4,%5,%6,%7}, {%8,%9}, {%0,%1,%2,%3};"
        : "+f"(d[0]), "+f"(d[1]), "+f"(d[2]), "+f"(d[3])
        : "r"(a[0]), "r"(a[1]), "r"(a[2]), "r"(a[3]),
          "r"(b[0]), "r"(b[1]));
}
__device__ __forceinline__ void ldsm4(uint32_t (&r)[4], uint32_t saddr) {
    asm volatile("ldmatrix.sync.aligned.m8n8.x4.shared.b16 {%0,%1,%2,%3}, [%4];"
                 : "=r"(r[0]), "=r"(r[1]), "=r"(r[2]), "=r"(r[3]) : "r"(saddr));
}

// ---------------------------------------------------------------------------
// Pre-conversion: fp32 -> packed bf16x2 hi/lo planes.
// ---------------------------------------------------------------------------
__global__ void __launch_bounds__(256) convert_kernel(
    const float* __restrict__ x,
    const float* __restrict__ Wq, const float* __restrict__ Wk,
    const float* __restrict__ Wv, const float* __restrict__ Wo)
{
    const int y = blockIdx.y;
    const float* src;
    uint32_t *dh, *dl;
    if (y < 4) { src = x + (size_t)y * 1048576; dh = g_xh + (size_t)y*524288; dl = g_xl + (size_t)y*524288; }
    else {
        src = (y == 4) ? Wq : (y == 5) ? Wk : (y == 6) ? Wv : Wo;
        dh = g_Wh[y-4]; dl = g_Wl[y-4];
    }
    const int idx = blockIdx.x * 256 + threadIdx.x;
    float4 v = ((const float4*)src)[idx];
    float h0 = bf_hi(v.x), h1 = bf_hi(v.y), h2 = bf_hi(v.z), h3 = bf_hi(v.w);
    ((uint2*)dh)[idx] = make_uint2(pack_bf2(h0, h1), pack_bf2(h2, h3));
    ((uint2*)dl)[idx] = make_uint2(pack_bf2(v.x-h0, v.y-h1), pack_bf2(v.z-h2, v.w-h3));
}

// ---------------------------------------------------------------------------
// bf16 2-split GEMM core. Tile 128x128, K=1024 in 64 stages of k16.
// 4 buffers x 16 KB, cp.async issue-ahead-3, SINGLE barrier per stage
// (write target's last reader is stage s-1, fenced by the stage-top barrier).
// Swizzle: phys_chunk = chunk ^ ((row>>2)&1)  (32 B rows, 2 chunks) --
// verified conflict-free for all ldmatrix phases and cp.async stores.
// ---------------------------------------------------------------------------
#define NS2 64

__device__ __forceinline__ void mma_gemm_pl(
    const uint32_t* __restrict__ Aph, const uint32_t* __restrict__ Apl,
    const uint32_t* __restrict__ Bph, const uint32_t* __restrict__ Bpl,
    int m0, int n0, float (&acc)[4][4][4], uint32_t* sm)
{
    const int tid  = threadIdx.x;
    const int lane = tid & 31;
    const int warp = tid >> 5;
    const int wm   = (warp >> 2) * 64;
    const int wn   = (warp & 3) * 32;

    const uint32_t sbase = (uint32_t)__cvta_generic_to_shared(sm);

    const int pl = tid >> 6, u = tid & 63;
    const uint32_t* gp = (pl == 0) ? Aph : (pl == 1) ? Apl
                        : (pl == 2) ? Bph : Bpl;
    const int rbase = (pl < 2) ? m0 : n0;

    // 4 planes x 128 rows x 2 chunks(16B); plane stride 4096 B, buf 16384 B
    #define ISSUE(S) do {                                                    \
        _Pragma("unroll")                                                    \
        for (int i = 0; i < 4; i++) {                                        \
            const int id  = i*64 + u;                                        \
            const int row = id >> 1, ch = id & 1;                            \
            const int phys = ch ^ ((row >> 2) & 1);                          \
            const uint32_t dst = sbase + ((S) & 3)*16384u + pl*4096u         \
                               + row*32u + phys*16u;                         \
            const uint32_t* srcp = gp + (size_t)(rbase + row)*LDP            \
                               + (S)*8 + ch*4;                               \
            asm volatile("cp.async.cg.shared.global [%0], [%1], 16;"         \
                         :: "r"(dst), "l"(srcp));                            \
        }                                                                    \
        asm volatile("cp.async.commit_group;");                              \
    } while (0)

    ISSUE(0); ISSUE(1); ISSUE(2);

    #pragma unroll 1
    for (int s = 0; s < NS2; s++) {
        if (s <= NS2 - 3)      asm volatile("cp.async.wait_group 2;");
        else if (s == NS2 - 2) asm volatile("cp.async.wait_group 1;");
        else                   asm volatile("cp.async.wait_group 0;");
        __syncthreads();
        if (s + 3 < NS2) ISSUE(s + 3);

        const uint32_t bb = sbase + (s & 3)*16384u;

        uint32_t ah[4][4], al[4][4];
        #pragma unroll
        for (int mt = 0; mt < 4; mt++) {
            const int row  = wm + mt*16 + (lane & 15);
            const int ch   = lane >> 4;
            const int phys = ch ^ ((row >> 2) & 1);
            const uint32_t ad = bb + row*32u + phys*16u;
            ldsm4(ah[mt], ad);              // Ah plane (offset 0)
            ldsm4(al[mt], ad + 4096u);      // Al plane
        }
        #pragma unroll
        for (int np = 0; np < 2; np++) {
            const int row  = wn + np*16 + (lane & 7) + ((lane & 16) ? 8 : 0);
            const int ch   = (lane >> 3) & 1;
            const int phys = ch ^ ((row >> 2) & 1);
            const uint32_t bd = bb + 8192u + row*32u + phys*16u;
            uint32_t bh4[4], bl4[4];
            ldsm4(bh4, bd);                 // Bh plane
            ldsm4(bl4, bd + 4096u);         // Bl plane
            uint32_t b0h[2] = {bh4[0], bh4[1]}, b1h[2] = {bh4[2], bh4[3]};
            uint32_t b0l[2] = {bl4[0], bl4[1]}, b1l[2] = {bl4[2], bl4[3]};
            // term 0: hi*hi (8 independent HMMAs)
            #pragma unroll
            for (int mt = 0; mt < 4; mt++) {
                mma16(acc[mt][2*np],   ah[mt], b0h);
                mma16(acc[mt][2*np+1], ah[mt], b1h);
            }
            // term 1: lo*hi
            #pragma unroll
            for (int mt = 0; mt < 4; mt++) {
                mma16(acc[mt][2*np],   al[mt], b0h);
                mma16(acc[mt][2*np+1], al[mt], b1h);
            }
            // term 2: hi*lo
            #pragma unroll
            for (int mt = 0; mt < 4; mt++) {
                mma16(acc[mt][2*np],   ah[mt], b0l);
                mma16(acc[mt][2*np+1], ah[mt], b1l);
            }
        }
    }
    #undef ISSUE
}

// ---------------------------------------------------------------------------
// Fused QKV projection. blockIdx.y: 0-7 Q, 8-15 K, 16-23 V.
// ---------------------------------------------------------------------------
__global__ void __launch_bounds__(256, 2) qkv_kernel(
    const float* __restrict__ bq, const float* __restrict__ bk,
    const float* __restrict__ bv)
{
    extern __shared__ uint32_t sm[];

    const int m0    = blockIdx.x * 128;
    const int tnn   = blockIdx.y;
    const int which = tnn >> 3;
    const int n0    = (tnn & 7) * 128;
    const float* bias = (which == 0) ? bq : ((which == 1) ? bk : bv);

    float acc[4][4][4];
    #pragma unroll
    for (int i = 0; i < 4; i++)
        #pragma unroll
        for (int j = 0; j < 4; j++)
            #pragma unroll
            for (int c = 0; c < 4; c++) acc[i][j][c] = 0.f;

    mma_gemm_pl(g_xh, g_xl, g_Wh[which], g_Wl[which], m0, n0, acc, sm);

    const int lane = threadIdx.x & 31;
    const int warp = threadIdx.x >> 5;
    const int wm = (warp >> 2) * 64;
    const int wn = (warp & 3) * 32;
    const bool evenrow = ((lane >> 2) & 1) == 0;

    #pragma unroll
    for (int mt = 0; mt < 4; mt++) {
        #pragma unroll
        for (int half = 0; half < 2; half++) {
            const int row = m0 + wm + mt*16 + (lane >> 2) + half*8;
            const int b   = row >> 11;
            const int tok = row & 2047;
            #pragma unroll
            for (int nt = 0; nt < 4; nt++) {
                const int col = n0 + wn + nt*8 + 2*(lane & 3);
                float v0 = acc[mt][nt][half*2+0] + bias[col];
                float v1 = acc[mt][nt][half*2+1] + bias[col+1];
                const int h = col >> 6, d = col & 63;
                if (which == 2) {
                    float p0 = __shfl_xor_sync(0xffffffffu, v0, 4);
                    float p1 = __shfl_xor_sync(0xffffffffu, v1, 4);
                    if (evenrow) {
                        const size_t idx0 =
                            ((size_t)(b*NHEAD + h)*HEAD_DIM + d)*(SEQ/2) + (tok >> 1);
                        float h0 = bf_hi(v0), hp0 = bf_hi(p0);
                        g_Vh[idx0] = pack_bf2(h0, hp0);
                        g_Vl[idx0] = pack_bf2(v0 - h0, p0 - hp0);
                        float h1 = bf_hi(v1), hp1 = bf_hi(p1);
                        g_Vh[idx0 + (SEQ/2)] = pack_bf2(h1, hp1);
                        g_Vl[idx0 + (SEQ/2)] = pack_bf2(v1 - h1, p1 - hp1);
                    }
                } else {
                    if (which == 0) { v0 = (2.f*v0 - 1.f)*0.125f; v1 = (2.f*v1 - 1.f)*0.125f; }
                    else            { v0 = 2.f*v0 - 1.f;          v1 = 2.f*v1 - 1.f; }
                    float h0 = bf_hi(v0), h1 = bf_hi(v1);
                    const size_t w = (((size_t)(b*NHEAD + h))*SEQ + tok)*32 + (d >> 1);
                    if (which == 0) {
                        g_Qh[w] = pack_bf2(h0, h1);
                        g_Ql[w] = pack_bf2(v0 - h0, v1 - h1);
                    } else {
                        g_Kh[w] = pack_bf2(h0, h1);
                        g_Kl[w] = pack_bf2(v0 - h0, v1 - h1);
                    }
                }
            }
        }
    }
}

// ---------------------------------------------------------------------------
// Flash attention, bf16 2-split, cp.async double-buffered K/V copies.
// ---------------------------------------------------------------------------
__global__ void __launch_bounds__(256, 2) flash_kernel()
{
    extern __shared__ uint32_t fsm[];

    const int bh = blockIdx.y;
    const int q0 = blockIdx.x * 128;
    const uint32_t* Qhp = g_Qh + (size_t)bh * SEQ * 32;
    const uint32_t* Qlp = g_Ql + (size_t)bh * SEQ * 32;
    const uint32_t* Khp = g_Kh + (size_t)bh * SEQ * 32;
    const uint32_t* Klp = g_Kl + (size_t)bh * SEQ * 32;
    const size_t    vbase = (size_t)bh * HEAD_DIM * (SEQ/2);

    const int tid  = threadIdx.x;
    const int lane = tid & 31;
    const int warp = tid >> 5;
    const int l4   = lane >> 2;
    const int lk   = lane & 3;
    const int r0   = warp*16 + l4;

    const uint32_t sb = (uint32_t)__cvta_generic_to_shared(fsm);

    #define FISSUE(T, BUF) do {                                              \
        _Pragma("unroll")                                                    \
        for (int it = 0; it < 8; it++) {                                     \
            const int id  = it*256 + tid;                                    \
            const int pl  = id >> 9;                                         \
            const int rid = id & 511;                                        \
            const int row = rid >> 3, ch = (rid & 7) * 4;                    \
            const uint32_t* src;                                             \
            if      (pl == 0) src = Khp + (size_t)((T)*64 + row)*32 + ch;    \
            else if (pl == 1) src = Klp + (size_t)((T)*64 + row)*32 + ch;    \
            else if (pl == 2) src = g_Vh + vbase + (size_t)row*(SEQ/2) + (T)*32 + ch; \
            else              src = g_Vl + vbase + (size_t)row*(SEQ/2) + (T)*32 + ch; \
            uint32_t dst = sb + (((BUF)*9216 + pl*2304 + row*36 + ch) << 2); \
            asm volatile("cp.async.cg.shared.global [%0], [%1], 16;"         \
                         :: "r"(dst), "l"(src));                             \
        }                                                                    \
        asm volatile("cp.async.commit_group;");                              \
    } while (0)

    uint32_t qh[4][4], ql[4][4];
    {
        const size_t r0w = (size_t)(q0 + r0) * 32;
        const size_t r1w = r0w + 8*32;
        #pragma unroll
        for (int kg = 0; kg < 4; kg++) {
            const int w = kg*8 + lk;
            qh[kg][0] = Qhp[r0w + w];     qh[kg][1] = Qhp[r1w + w];
            qh[kg][2] = Qhp[r0w + w + 4]; qh[kg][3] = Qhp[r1w + w + 4];
            ql[kg][0] = Qlp[r0w + w];     ql[kg][1] = Qlp[r1w + w];
            ql[kg][2] = Qlp[r0w + w + 4]; ql[kg][3] = Qlp[r1w + w + 4];
        }
    }

    float m_i[2] = {-1e30f, -1e30f};
    float l_i[2] = {0.f, 0.f};
    float o[8][4];
    #pragma unroll
    for (int nt = 0; nt < 8; nt++)
        #pragma unroll
        for (int c = 0; c < 4; c++) o[nt][c] = 0.f;

    FISSUE(0, 0);

    int buf = 0;
    #pragma unroll 1
    for (int t = 0; t < SEQ/64; t++) {
        if (t + 1 < SEQ/64) {
            FISSUE(t + 1, buf ^ 1);
            asm volatile("cp.async.wait_group 1;");
        } else {
            asm volatile("cp.async.wait_group 0;");
        }
        __syncthreads();

        const uint32_t* Ksh = fsm + buf*9216;
        const uint32_t* Ksl = Ksh + 2304;
        const uint32_t* Vsh = Ksh + 4608;
        const uint32_t* Vsl = Ksh + 6912;

        float s[8][4];
        #pragma unroll
        for (int nt = 0; nt < 8; nt++)
            #pragma unroll
            for (int c = 0; c < 4; c++) s[nt][c] = 0.f;

        #pragma unroll
        for (int kg = 0; kg < 4; kg++) {
            const int kw = kg*8 + lk;
            #pragma unroll
            for (int g = 0; g < 2; g++) {
                uint32_t fh[4][2], fl[4][2];
                #pragma unroll
                for (int j = 0; j < 4; j++) {
                    const int n = (g*4 + j)*8 + l4;
                    fh[j][0] = Ksh[n*36 + kw]; fh[j][1] = Ksh[n*36 + kw + 4];
                    fl[j][0] = Ksl[n*36 + kw]; fl[j][1] = Ksl[n*36 + kw + 4];
                }
                #pragma unroll
                for (int j = 0; j < 4; j++) mma16(s[g*4+j], qh[kg], fh[j]);
                #pragma unroll
                for (int j = 0; j < 4; j++) mma16(s[g*4+j], ql[kg], fh[j]);
                #pragma unroll
                for (int j = 0; j < 4; j++) mma16(s[g*4+j], qh[kg], fl[j]);
            }
        }

        float mx0 = -1e30f, mx1 = -1e30f;
        #pragma unroll
        for (int nt = 0; nt < 8; nt++) {
            mx0 = fmaxf(mx0, fmaxf(s[nt][0], s[nt][1]));
            mx1 = fmaxf(mx1, fmaxf(s[nt][2], s[nt][3]));
        }
        mx0 = fmaxf(mx0, __shfl_xor_sync(0xffffffffu, mx0, 1));
        mx0 = fmaxf(mx0, __shfl_xor_sync(0xffffffffu, mx0, 2));
        mx1 = fmaxf(mx1, __shfl_xor_sync(0xffffffffu, mx1, 1));
        mx1 = fmaxf(mx1, __shfl_xor_sync(0xffffffffu, mx1, 2));

        const float nm0 = fmaxf(m_i[0], mx0);
        const float nm1 = fmaxf(m_i[1], mx1);
        const float cr0 = __expf(m_i[0] - nm0);
        const float cr1 = __expf(m_i[1] - nm1);
        m_i[0] = nm0; m_i[1] = nm1;

        float rs0 = 0.f, rs1 = 0.f;
        #pragma unroll
        for (int nt = 0; nt < 8; nt++) {
            s[nt][0] = __expf(s[nt][0] - nm0);
            s[nt][1] = __expf(s[nt][1] - nm0);
            s[nt][2] = __expf(s[nt][2] - nm1);
            s[nt][3] = __expf(s[nt][3] - nm1);
            rs0 += s[nt][0] + s[nt][1];
            rs1 += s[nt][2] + s[nt][3];
        }
        rs0 += __shfl_xor_sync(0xffffffffu, rs0, 1);
        rs0 += __shfl_xor_sync(0xffffffffu, rs0, 2);
        rs1 += __shfl_xor_sync(0xffffffffu, rs1, 1);
        rs1 += __shfl_xor_sync(0xffffffffu, rs1, 2);
        l_i[0] = l_i[0]*cr0 + rs0;
        l_i[1] = l_i[1]*cr1 + rs1;

        #pragma unroll
        for (int nt = 0; nt < 8; nt++) {
            o[nt][0] *= cr0; o[nt][1] *= cr0;
            o[nt][2] *= cr1; o[nt][3] *= cr1;
        }

        #pragma unroll
        for (int kg = 0; kg < 4; kg++) {
            float h00 = bf_hi(s[2*kg][0]),   h01 = bf_hi(s[2*kg][1]);
            float h02 = bf_hi(s[2*kg][2]),   h03 = bf_hi(s[2*kg][3]);
            float h10 = bf_hi(s[2*kg+1][0]), h11 = bf_hi(s[2*kg+1][1]);
            float h12 = bf_hi(s[2*kg+1][2]), h13 = bf_hi(s[2*kg+1][3]);
            uint32_t pah[4] = {
                pack_bf2(h00, h01), pack_bf2(h02, h03),
                pack_bf2(h10, h11), pack_bf2(h12, h13) };
            uint32_t pal[4] = {
                pack_bf2(s[2*kg][0]-h00,   s[2*kg][1]-h01),
                pack_bf2(s[2*kg][2]-h02,   s[2*kg][3]-h03),
                pack_bf2(s[2*kg+1][0]-h10, s[2*kg+1][1]-h11),
                pack_bf2(s[2*kg+1][2]-h12, s[2*kg+1][3]-h13) };
            const int kw = kg*8 + lk;
            #pragma unroll
            for (int g = 0; g < 2; g++) {
                uint32_t fh[4][2], fl[4][2];
                #pragma unroll
                for (int j = 0; j < 4; j++) {
                    const int n = (g*4 + j)*8 + l4;
                    fh[j][0] = Vsh[n*36 + kw]; fh[j][1] = Vsh[n*36 + kw + 4];
                    fl[j][0] = Vsl[n*36 + kw]; fl[j][1] = Vsl[n*36 + kw + 4];
                }
                #pragma unroll
                for (int j = 0; j < 4; j++) mma16(o[g*4+j], pah, fh[j]);
                #pragma unroll
                for (int j = 0; j < 4; j++) mma16(o[g*4+j], pal, fh[j]);
                #pragma unroll
                for (int j = 0; j < 4; j++) mma16(o[g*4+j], pah, fl[j]);
            }
        }
        __syncthreads();
        buf ^= 1;
    }
    #undef FISSUE

    const int b = bh >> 4;
    const int h = bh & 15;
    const float inv0 = 1.f / l_i[0];
    const float inv1 = 1.f / l_i[1];
    const size_t m0r = (size_t)(b*SEQ + q0 + r0);
    #pragma unroll
    for (int nt = 0; nt < 8; nt++) {
        const int w = h*32 + nt*4 + lk;
        float v0 = o[nt][0]*inv0, v1 = o[nt][1]*inv0;
        float h0 = bf_hi(v0), h1 = bf_hi(v1);
        g_Ah[m0r*LDP + w] = pack_bf2(h0, h1);
        g_Al[m0r*LDP + w] = pack_bf2(v0 - h0, v1 - h1);
        float v2 = o[nt][2]*inv1, v3 = o[nt][3]*inv1;
        float h2 = bf_hi(v2), h3 = bf_hi(v3);
        g_Ah[(m0r+8)*LDP + w] = pack_bf2(h2, h3);
        g_Al[(m0r+8)*LDP + w] = pack_bf2(v2 - h2, v3 - h3);
    }
}

// ---------------------------------------------------------------------------
// Output projection: d_out = A @ Wo^T + bo
// ---------------------------------------------------------------------------
__global__ void __launch_bounds__(256, 2) proj_kernel(
    const float* __restrict__ bo, float* __restrict__ out)
{
    extern __shared__ uint32_t sm[];

    const int m0 = blockIdx.x * 128;
    const int n0 = blockIdx.y * 128;

    float acc[4][4][4];
    #pragma unroll
    for (int i = 0; i < 4; i++)
        #pragma unroll
        for (int j = 0; j < 4; j++)
            #pragma unroll
            for (int c = 0; c < 4; c++) acc[i][j][c] = 0.f;

    mma_gemm_pl(g_Ah, g_Al, g_Wh[3], g_Wl[3], m0, n0, acc, sm);

    const int lane = threadIdx.x & 31;
    const int warp = threadIdx.x >> 5;
    const int wm = (warp >> 2) * 64;
    const int wn = (warp & 3) * 32;

    #pragma unroll
    for (int mt = 0; mt < 4; mt++) {
        #pragma unroll
        for (int half = 0; half < 2; half++) {
            const int row = m0 + wm + mt*16 + (lane >> 2) + half*8;
            #pragma unroll
            for (int nt = 0; nt < 4; nt++) {
                const int col = n0 + wn + nt*8 + 2*(lane & 3);
                float v0 = acc[mt][nt][half*2+0] + bo[col];
                float v1 = acc[mt][nt][half*2+1] + bo[col+1];
                *(float2*)(out + (size_t)row * D_MODEL + col) = make_float2(v0, v1);
            }
        }
    }
}

extern "C" void kernel_launch(void* const* d_in, const int* in_sizes, int n_in,
                              void* d_out, int out_size)
{
    const float* x  = (const float*)d_in[0];
    const float* Wq = (const float*)d_in[1];
    const float* bq = (const float*)d_in[2];
    const float* Wk = (const float*)d_in[3];
    const float* bk = (const float*)d_in[4];
    const float* Wv = (const float*)d_in[5];
    const float* bv = (const float*)d_in[6];
    const float* Wo = (const float*)d_in[7];
    const float* bo = (const float*)d_in[8];
    float* out = (float*)d_out;

    const int gsmem = 4 * 16384;              // 65536 B (4-buffer pipeline)
    const int fsmem = 2 * 4 * 2304 * 4;       // 73728 B
    cudaFuncSetAttribute(qkv_kernel,
                         cudaFuncAttributeMaxDynamicSharedMemorySize, gsmem);
    cudaFuncSetAttribute(proj_kernel,
                         cudaFuncAttributeMaxDynamicSharedMemorySize, gsmem);
    cudaFuncSetAttribute(flash_kernel,
                         cudaFuncAttributeMaxDynamicSharedMemorySize, fsmem);

    convert_kernel<<<dim3(1024, 8), 256>>>(x, Wq, Wk, Wv, Wo);
    qkv_kernel<<<dim3(32, 24), 256, gsmem>>>(bq, bk, bv);
    flash_kernel<<<dim3(SEQ/128, BATCH*NHEAD), 256, fsmem>>>();
    proj_kernel<<<dim3(32, 8), 256, gsmem>>>(bo, out);
}